// round 6
// baseline (speedup 1.0000x reference)
#include <cuda_runtime.h>

#define FULL 0xffffffffu
typedef unsigned long long ull;

__device__ __forceinline__ float relu_(float v) { return fmaxf(v, 0.0f); }

__device__ __forceinline__ ull ffma2(ull a, ull b, ull c) {
    ull d; asm("fma.rn.f32x2 %0, %1, %2, %3;" : "=l"(d) : "l"(a), "l"(b), "l"(c)); return d;
}
__device__ __forceinline__ ull fadd2(ull a, ull b) {
    ull d; asm("add.rn.f32x2 %0, %1, %2;" : "=l"(d) : "l"(a), "l"(b)); return d;
}
__device__ __forceinline__ ull pk2(float lo, float hi) {
    ull r; asm("mov.b64 %0, {%1, %2};" : "=l"(r) : "f"(lo), "f"(hi)); return r;
}
__device__ __forceinline__ void upk2(ull v, float& lo, float& hi) {
    asm("mov.b64 {%0, %1}, %2;" : "=f"(lo), "=f"(hi) : "l"(v));
}
__device__ __forceinline__ ull relu2(ull v) {
    float lo, hi; upk2(v, lo, hi);
    return pk2(fmaxf(lo, 0.0f), fmaxf(hi, 0.0f));
}

// ---------------- constant blob layout (floats) ----------------
// [0]    oW1 neuron-pair-major: [t][d][e] = W1[d][2t+e]   (128)
// [128]  ob1                                              (32)
// [160]  oW2t [j*32+i]                                    (1024)
// [1184] ob2                                              (32)
// [1216] oW3 [j*16+k]                                     (512)
// [1728] ob3                                              (16)
#define CW_TOTAL 1744
__constant__ __align__(16) float c_w[CW_TOTAL];
__device__   __align__(16) float g_blob[CW_TOTAL];

__global__ void pack_kernel(const float* __restrict__ oW1, const float* __restrict__ ob1,
                            const float* __restrict__ oW2, const float* __restrict__ ob2,
                            const float* __restrict__ oW3, const float* __restrict__ ob3)
{
    int t = threadIdx.x;
    if (t < 128) {
        int tt = t >> 3, d = (t >> 1) & 3, e = t & 1;
        g_blob[t] = oW1[d * 32 + 2 * tt + e];
    }
    if (t < 32) g_blob[128 + t] = ob1[t];
    for (int idx = t; idx < 1024; idx += 256) {
        int j = idx >> 5, i = idx & 31;
        g_blob[160 + j * 32 + i] = oW2[i * 32 + j];
    }
    if (t < 32) g_blob[1184 + t] = ob2[t];
    for (int idx = t; idx < 512; idx += 256) g_blob[1216 + idx] = oW3[idx];
    if (t < 16) g_blob[1728 + t] = ob3[t];
}

// Padded stride for lane-indexed shared tables (bank-conflict-free)
#define PSTR 36

// R=1: one warp per batch row; lane = agent. Low register state ->
// 3 CTAs/SM (24 warps) to hide latency and push the fma pipe toward its wall.
__global__ __launch_bounds__(256, 3)
void dqv_kernel(const float* __restrict__ x,
                const int*   __restrict__ selp,
                const float* __restrict__ sW1, const float* __restrict__ sb1,
                const float* __restrict__ sW2, const float* __restrict__ sb2,
                const float* __restrict__ sW3, const float* __restrict__ sb3,
                const float* __restrict__ gW1, const float* __restrict__ gb1,
                const float* __restrict__ gW2, const float* __restrict__ gb2,
                float* __restrict__ out_q)
{
    __shared__ __align__(16) float s_sW1t[32 * 4];   // [n][d]
    __shared__             float s_sb1[32];
    __shared__ __align__(16) float s_sW2t[32 * PSTR]; // [n][i] padded
    __shared__             float s_sb2[32];
    __shared__             float s_sW3[32 * 16];      // [j][k]
    __shared__             float s_sb3[16];
    __shared__ __align__(16) float s_gW1t[32 * PSTR]; // [m][c] padded
    __shared__             float s_gb1[32];
    __shared__             float s_gW2[64];
    __shared__             float s_gb2[2];

    const int tid = threadIdx.x;

    for (int idx = tid; idx < 128; idx += 256) {
        int d = idx >> 5, n = idx & 31;
        s_sW1t[n * 4 + d] = sW1[idx];
    }
    for (int idx = tid; idx < 1024; idx += 256) {
        int i = idx >> 5, j = idx & 31;
        s_sW2t[j * PSTR + i] = sW2[idx];
        s_gW1t[j * PSTR + i] = gW1[idx];
    }
    for (int idx = tid; idx < 512; idx += 256) s_sW3[idx] = sW3[idx];
    if (tid < 32) { s_sb1[tid] = sb1[tid]; s_sb2[tid] = sb2[tid]; s_gb1[tid] = gb1[tid]; }
    if (tid >= 48 && tid < 64)  s_sb3[tid - 48] = sb3[tid - 48];
    if (tid >= 64 && tid < 128) s_gW2[tid - 64] = gW2[tid - 64];
    if (tid >= 128 && tid < 130) s_gb2[tid - 128] = gb2[tid - 128];
    __syncthreads();

    const int lane = tid & 31;
    const int warp = tid >> 5;
    const int row  = blockIdx.x * 8 + warp;
    const int sel  = selp[0];

    const float4 xa = reinterpret_cast<const float4*>(x)[row * 32 + lane];

    // ---------------- layer 1 (constant, neuron-pair packed FFMA2) ----------------
    ull xd0 = pk2(xa.x, xa.x), xd1 = pk2(xa.y, xa.y);
    ull xd2 = pk2(xa.z, xa.z), xd3 = pk2(xa.w, xa.w);

    ull h1[16];   // (h1[2t], h1[2t+1])
    {
        const ulonglong2* w1 = reinterpret_cast<const ulonglong2*>(c_w);
        const ull* b1 = reinterpret_cast<const ull*>(c_w + 128);
        #pragma unroll
        for (int t = 0; t < 16; ++t) {
            ulonglong2 wA = w1[2 * t + 0];
            ulonglong2 wB = w1[2 * t + 1];
            ull a = ffma2(xd0, wA.x, b1[t]);
            a = ffma2(xd1, wA.y, a);
            a = ffma2(xd2, wB.x, a);
            a = ffma2(xd3, wB.y, a);
            h1[t] = relu2(a);
        }
    }

    ull acc[8];
    {
        const ull* b3 = reinterpret_cast<const ull*>(c_w + 1728);
        #pragma unroll
        for (int t = 0; t < 8; ++t) acc[t] = b3[t];
    }

    // ---------------- layer 2 + layer 3 fused ----------------
    #pragma unroll 4
    for (int j = 0; j < 32; ++j) {
        ull a0 = 0ull;
        const ulonglong2* w2 = reinterpret_cast<const ulonglong2*>(c_w + 160 + j * 32);
        #pragma unroll
        for (int q = 0; q < 8; ++q) {
            ulonglong2 w = w2[q];
            a0 = ffma2(h1[2 * q + 0], w.x, a0);
            a0 = ffma2(h1[2 * q + 1], w.y, a0);
        }
        float l0, h0;
        upk2(a0, l0, h0);
        float s0 = relu_(l0 + h0 + c_w[1184 + j]);
        ull p0 = pk2(s0, s0);

        const ulonglong2* w3 = reinterpret_cast<const ulonglong2*>(c_w + 1216 + j * 16);
        #pragma unroll
        for (int r = 0; r < 4; ++r) {
            ulonglong2 w = w3[r];
            acc[2 * r + 0] = ffma2(p0, w.x, acc[2 * r + 0]);
            acc[2 * r + 1] = ffma2(p0, w.y, acc[2 * r + 1]);
        }
    }

    // prefetch selected-agent input (hide LDG under the reduce)
    const float4 xs = reinterpret_cast<const float4*>(x)[row * 32 + sel];

    // final relu + mask + packed butterfly reduce
    const float msk = (lane == sel) ? 0.0f : 1.0f;
    #pragma unroll
    for (int t = 0; t < 8; ++t) {
        float lo, hi;
        upk2(acc[t], lo, hi);
        acc[t] = pk2(relu_(lo) * msk, relu_(hi) * msk);
    }
    #pragma unroll
    for (int off = 16; off; off >>= 1) {
        #pragma unroll
        for (int t = 0; t < 8; ++t)
            acc[t] = fadd2(acc[t], __shfl_xor_sync(FULL, acc[t], off));
    }

    float so[16];
    #pragma unroll
    for (int t = 0; t < 8; ++t) upk2(acc[t], so[2 * t], so[2 * t + 1]);

    // ---------------- tail: sel MLP + gating head (scalar, warp-coop) ----------------
    float4 w1v = reinterpret_cast<const float4*>(s_sW1t)[lane];
    float sh1 = relu_(fmaf(xs.x, w1v.x, fmaf(xs.y, w1v.y, fmaf(xs.z, w1v.z, fmaf(xs.w, w1v.w, s_sb1[lane])))));

    float a2 = s_sb2[lane];
    #pragma unroll
    for (int q = 0; q < 8; ++q) {
        float4 w = *reinterpret_cast<const float4*>(s_sW2t + lane * PSTR + 4 * q);
        a2 = fmaf(__shfl_sync(FULL, sh1, 4 * q + 0), w.x, a2);
        a2 = fmaf(__shfl_sync(FULL, sh1, 4 * q + 1), w.y, a2);
        a2 = fmaf(__shfl_sync(FULL, sh1, 4 * q + 2), w.z, a2);
        a2 = fmaf(__shfl_sync(FULL, sh1, 4 * q + 3), w.w, a2);
    }
    const float sh2 = relu_(a2);

    const int k15 = lane & 15;
    float a3 = s_sb3[k15];
    #pragma unroll
    for (int j = 0; j < 32; ++j)
        a3 = fmaf(__shfl_sync(FULL, sh2, j), s_sW3[j * 16 + k15], a3);
    const float sel_out = relu_(a3);

    float ag = s_gb1[lane];
    #pragma unroll
    for (int m = 0; m < 4; ++m) {
        float4 w = *reinterpret_cast<const float4*>(s_gW1t + lane * PSTR + 4 * m);
        ag = fmaf(__shfl_sync(FULL, sel_out, 4 * m + 0), w.x, ag);
        ag = fmaf(__shfl_sync(FULL, sel_out, 4 * m + 1), w.y, ag);
        ag = fmaf(__shfl_sync(FULL, sel_out, 4 * m + 2), w.z, ag);
        ag = fmaf(__shfl_sync(FULL, sel_out, 4 * m + 3), w.w, ag);
    }
    #pragma unroll
    for (int m = 0; m < 4; ++m) {
        float4 w = *reinterpret_cast<const float4*>(s_gW1t + lane * PSTR + 16 + 4 * m);
        ag = fmaf(so[4 * m + 0], w.x, ag);
        ag = fmaf(so[4 * m + 1], w.y, ag);
        ag = fmaf(so[4 * m + 2], w.z, ag);
        ag = fmaf(so[4 * m + 3], w.w, ag);
    }
    const float hg = relu_(ag);

    float q0 = hg * s_gW2[lane * 2 + 0];
    float q1 = hg * s_gW2[lane * 2 + 1];
    #pragma unroll
    for (int off = 16; off; off >>= 1) {
        q0 += __shfl_xor_sync(FULL, q0, off);
        q1 += __shfl_xor_sync(FULL, q1, off);
    }

    if (lane == 0) {
        int act = (int)xs.w;
        act = act < 0 ? 0 : (act > 1 ? 1 : act);
        out_q[row] = act ? (q1 + s_gb2[1]) : (q0 + s_gb2[0]);
    }
}

extern "C" void kernel_launch(void* const* d_in, const int* in_sizes, int n_in,
                              void* d_out, int out_size)
{
    (void)in_sizes; (void)n_in; (void)out_size;

    pack_kernel<<<1, 256>>>(
        (const float*)d_in[2], (const float*)d_in[3],
        (const float*)d_in[4], (const float*)d_in[5],
        (const float*)d_in[6], (const float*)d_in[7]);

    void* dst = nullptr;
    void* src = nullptr;
    cudaGetSymbolAddress(&dst, c_w);
    cudaGetSymbolAddress(&src, g_blob);
    cudaMemcpyAsync(dst, src, CW_TOTAL * sizeof(float),
                    cudaMemcpyDeviceToDevice, 0);

    // B = 65536 rows; 8 warps/block x 1 row/warp -> 8192 blocks.
    dqv_kernel<<<8192, 256>>>(
        (const float*)d_in[0],  (const int*)d_in[1],
        (const float*)d_in[8],  (const float*)d_in[9],
        (const float*)d_in[10], (const float*)d_in[11],
        (const float*)d_in[12], (const float*)d_in[13],
        (const float*)d_in[14], (const float*)d_in[15],
        (const float*)d_in[16], (const float*)d_in[17],
        (float*)d_out);
}

// round 7
// speedup vs baseline: 1.4543x; 1.4543x over previous
#include <cuda_runtime.h>

#define FULL 0xffffffffu
typedef unsigned long long ull;

__device__ __forceinline__ float relu_(float v) { return fmaxf(v, 0.0f); }

__device__ __forceinline__ ull ffma2(ull a, ull b, ull c) {
    ull d; asm("fma.rn.f32x2 %0, %1, %2, %3;" : "=l"(d) : "l"(a), "l"(b), "l"(c)); return d;
}
__device__ __forceinline__ ull fadd2(ull a, ull b) {
    ull d; asm("add.rn.f32x2 %0, %1, %2;" : "=l"(d) : "l"(a), "l"(b)); return d;
}
__device__ __forceinline__ ull pk2(float lo, float hi) {
    ull r; asm("mov.b64 %0, {%1, %2};" : "=l"(r) : "f"(lo), "f"(hi)); return r;
}
__device__ __forceinline__ void upk2(ull v, float& lo, float& hi) {
    asm("mov.b64 {%0, %1}, %2;" : "=f"(lo), "=f"(hi) : "l"(v));
}
__device__ __forceinline__ ull relu2(ull v) {
    float lo, hi; upk2(v, lo, hi);
    return pk2(fmaxf(lo, 0.0f), fmaxf(hi, 0.0f));
}
__device__ __forceinline__ float hadd2(ull v) {
    float lo, hi; upk2(v, lo, hi); return lo + hi;
}

// ---------------- constant blob layout (floats) ----------------
// other-agent MLP:
//   [0]    oW1 pair-major [t][d][e] = oW1[d*32+2t+e] (128)
//   [128]  ob1 (32)
//   [160]  oW2t [j*32+i] (1024)
//   [1184] ob2 (32)
//   [1216] oW3 [j*16+k] (512)
//   [1728] ob3 (16)
// selected MLP + gating (for kernel B):
//   [1744] sW1 pair-major (128)
//   [1872] sb1 (32)
//   [1904] sW2t [j*32+i] (1024)
//   [2928] sb2 (32)
//   [2960] sW3 [j*16+k] (512)
//   [3472] sb3 (16)
//   [3488] gW1t [m*32+c] (1024)
//   [4512] gb1 (32)
//   [4544] gW2 [m*2+a] (64)
//   [4608] gb2 (2)
#define CW_TOTAL 4624
__constant__ __align__(16) float c_w[CW_TOTAL];
__device__   __align__(16) float g_blob[CW_TOTAL];

// scratch: sum_other per row, 8 packed ull (16 floats)
#define NROWS 65536
__device__ __align__(16) ull g_sum[NROWS * 8];

__global__ void pack_kernel(const float* __restrict__ oW1, const float* __restrict__ ob1,
                            const float* __restrict__ oW2, const float* __restrict__ ob2,
                            const float* __restrict__ oW3, const float* __restrict__ ob3,
                            const float* __restrict__ sW1, const float* __restrict__ sb1,
                            const float* __restrict__ sW2, const float* __restrict__ sb2,
                            const float* __restrict__ sW3, const float* __restrict__ sb3,
                            const float* __restrict__ gW1, const float* __restrict__ gb1,
                            const float* __restrict__ gW2, const float* __restrict__ gb2)
{
    int t = threadIdx.x;
    if (t < 128) {
        int tp = t >> 3, d = (t >> 1) & 3, e = t & 1;
        g_blob[t]        = oW1[d * 32 + 2 * tp + e];
        g_blob[1744 + t] = sW1[d * 32 + 2 * tp + e];
    }
    if (t < 32) {
        g_blob[128 + t]  = ob1[t];
        g_blob[1184 + t] = ob2[t];
        g_blob[1872 + t] = sb1[t];
        g_blob[2928 + t] = sb2[t];
        g_blob[4512 + t] = gb1[t];
    }
    for (int idx = t; idx < 1024; idx += 256) {
        int j = idx >> 5, i = idx & 31;
        g_blob[160  + j * 32 + i] = oW2[i * 32 + j];
        g_blob[1904 + j * 32 + i] = sW2[i * 32 + j];
        g_blob[3488 + j * 32 + i] = gW1[i * 32 + j];   // [m][c] = gW1[c*32+m]
    }
    for (int idx = t; idx < 512; idx += 256) {
        g_blob[1216 + idx] = oW3[idx];
        g_blob[2960 + idx] = sW3[idx];
    }
    if (t < 16) { g_blob[1728 + t] = ob3[t]; g_blob[3472 + t] = sb3[t]; }
    if (t >= 64 && t < 128) g_blob[4544 + t - 64] = gW2[t - 64];
    if (t >= 128 && t < 130) g_blob[4608 + t - 128] = gb2[t - 128];
}

// ---------------- Kernel A: other-agent MLP + masked sum ----------------
// One warp = two rows; lane = agent. All weights on the constant port.
// No shared memory, no syncthreads, no tail.
__global__ __launch_bounds__(256, 2)
void mainmlp_kernel(const float* __restrict__ x,
                    const int*   __restrict__ selp)
{
    const int tid  = threadIdx.x;
    const int lane = tid & 31;
    const int warp = tid >> 5;
    const int row0 = blockIdx.x * 16 + warp;
    const int row1 = row0 + 8;
    const int sel  = selp[0];

    const float4 xa0 = reinterpret_cast<const float4*>(x)[row0 * 32 + lane];
    const float4 xa1 = reinterpret_cast<const float4*>(x)[row1 * 32 + lane];

    // layer 1: neuron-pair packed
    ull x0d[4] = { pk2(xa0.x, xa0.x), pk2(xa0.y, xa0.y), pk2(xa0.z, xa0.z), pk2(xa0.w, xa0.w) };
    ull x1d[4] = { pk2(xa1.x, xa1.x), pk2(xa1.y, xa1.y), pk2(xa1.z, xa1.z), pk2(xa1.w, xa1.w) };

    ull h1a[16], h1b[16];
    {
        const ulonglong2* w1 = reinterpret_cast<const ulonglong2*>(c_w);
        const ull* b1 = reinterpret_cast<const ull*>(c_w + 128);
        #pragma unroll
        for (int t = 0; t < 16; ++t) {
            ulonglong2 wA = w1[2 * t + 0];
            ulonglong2 wB = w1[2 * t + 1];
            ull bb = b1[t];
            ull a0 = ffma2(x0d[0], wA.x, bb);
            a0 = ffma2(x0d[1], wA.y, a0);
            a0 = ffma2(x0d[2], wB.x, a0);
            a0 = ffma2(x0d[3], wB.y, a0);
            h1a[t] = relu2(a0);
            ull a1 = ffma2(x1d[0], wA.x, bb);
            a1 = ffma2(x1d[1], wA.y, a1);
            a1 = ffma2(x1d[2], wB.x, a1);
            a1 = ffma2(x1d[3], wB.y, a1);
            h1b[t] = relu2(a1);
        }
    }

    ull accA[8], accB[8];
    {
        const ull* b3 = reinterpret_cast<const ull*>(c_w + 1728);
        #pragma unroll
        for (int t = 0; t < 8; ++t) { accA[t] = b3[t]; accB[t] = b3[t]; }
    }

    // layer 2 + 3 fused
    #pragma unroll 4
    for (int j = 0; j < 32; ++j) {
        ull a0 = 0ull, a1 = 0ull;
        const ulonglong2* w2 = reinterpret_cast<const ulonglong2*>(c_w + 160 + j * 32);
        #pragma unroll
        for (int q = 0; q < 8; ++q) {
            ulonglong2 w = w2[q];
            a0 = ffma2(h1a[2 * q + 0], w.x, a0);
            a0 = ffma2(h1a[2 * q + 1], w.y, a0);
            a1 = ffma2(h1b[2 * q + 0], w.x, a1);
            a1 = ffma2(h1b[2 * q + 1], w.y, a1);
        }
        float bj = c_w[1184 + j];
        float s0 = relu_(hadd2(a0) + bj);
        float s1 = relu_(hadd2(a1) + bj);
        ull p0 = pk2(s0, s0);
        ull p1 = pk2(s1, s1);

        const ulonglong2* w3 = reinterpret_cast<const ulonglong2*>(c_w + 1216 + j * 16);
        #pragma unroll
        for (int r = 0; r < 4; ++r) {
            ulonglong2 w = w3[r];
            accA[2 * r + 0] = ffma2(p0, w.x, accA[2 * r + 0]);
            accA[2 * r + 1] = ffma2(p0, w.y, accA[2 * r + 1]);
            accB[2 * r + 0] = ffma2(p1, w.x, accB[2 * r + 0]);
            accB[2 * r + 1] = ffma2(p1, w.y, accB[2 * r + 1]);
        }
    }

    // final relu + mask + packed butterfly reduce
    const float msk = (lane == sel) ? 0.0f : 1.0f;
    #pragma unroll
    for (int t = 0; t < 8; ++t) {
        float lo, hi;
        upk2(accA[t], lo, hi);
        accA[t] = pk2(relu_(lo) * msk, relu_(hi) * msk);
        upk2(accB[t], lo, hi);
        accB[t] = pk2(relu_(lo) * msk, relu_(hi) * msk);
    }
    #pragma unroll
    for (int off = 16; off; off >>= 1) {
        #pragma unroll
        for (int t = 0; t < 8; ++t) {
            accA[t] = fadd2(accA[t], __shfl_xor_sync(FULL, accA[t], off));
            accB[t] = fadd2(accB[t], __shfl_xor_sync(FULL, accB[t], off));
        }
    }

    // all lanes hold the full sums; lane 0 stores row0, lane 16 stores row1
    if (lane == 0) {
        ulonglong2* dst = reinterpret_cast<ulonglong2*>(g_sum + (size_t)row0 * 8);
        dst[0] = make_ulonglong2(accA[0], accA[1]);
        dst[1] = make_ulonglong2(accA[2], accA[3]);
        dst[2] = make_ulonglong2(accA[4], accA[5]);
        dst[3] = make_ulonglong2(accA[6], accA[7]);
    } else if (lane == 16) {
        ulonglong2* dst = reinterpret_cast<ulonglong2*>(g_sum + (size_t)row1 * 8);
        dst[0] = make_ulonglong2(accB[0], accB[1]);
        dst[1] = make_ulonglong2(accB[2], accB[3]);
        dst[2] = make_ulonglong2(accB[4], accB[5]);
        dst[3] = make_ulonglong2(accB[6], accB[7]);
    }
}

// ---------------- Kernel B: tail, lane = row, all-uniform weights ----------------
__global__ __launch_bounds__(256)
void tail_kernel(const float* __restrict__ x,
                 const int*   __restrict__ selp,
                 float* __restrict__ out_q)
{
    const int row = blockIdx.x * 256 + threadIdx.x;
    const int sel = selp[0];

    const float4 xs = reinterpret_cast<const float4*>(x)[row * 32 + sel];

    ull so_p[8];
    {
        const ulonglong2* src = reinterpret_cast<const ulonglong2*>(g_sum + (size_t)row * 8);
        #pragma unroll
        for (int r = 0; r < 4; ++r) {
            ulonglong2 v = src[r];
            so_p[2 * r + 0] = v.x;
            so_p[2 * r + 1] = v.y;
        }
    }

    // sel layer1 (pair-packed)
    ull xd0 = pk2(xs.x, xs.x), xd1 = pk2(xs.y, xs.y);
    ull xd2 = pk2(xs.z, xs.z), xd3 = pk2(xs.w, xs.w);
    ull h1[16];
    {
        const ulonglong2* w1 = reinterpret_cast<const ulonglong2*>(c_w + 1744);
        const ull* b1 = reinterpret_cast<const ull*>(c_w + 1872);
        #pragma unroll
        for (int t = 0; t < 16; ++t) {
            ulonglong2 wA = w1[2 * t + 0];
            ulonglong2 wB = w1[2 * t + 1];
            ull a = ffma2(xd0, wA.x, b1[t]);
            a = ffma2(xd1, wA.y, a);
            a = ffma2(xd2, wB.x, a);
            a = ffma2(xd3, wB.y, a);
            h1[t] = relu2(a);
        }
    }

    // sel layer2+3 fused
    ull acc3[8];
    {
        const ull* b3 = reinterpret_cast<const ull*>(c_w + 3472);
        #pragma unroll
        for (int t = 0; t < 8; ++t) acc3[t] = b3[t];
    }
    #pragma unroll 4
    for (int j = 0; j < 32; ++j) {
        ull a = 0ull;
        const ulonglong2* w2 = reinterpret_cast<const ulonglong2*>(c_w + 1904 + j * 32);
        #pragma unroll
        for (int q = 0; q < 8; ++q) {
            ulonglong2 w = w2[q];
            a = ffma2(h1[2 * q + 0], w.x, a);
            a = ffma2(h1[2 * q + 1], w.y, a);
        }
        float s = relu_(hadd2(a) + c_w[2928 + j]);
        ull p = pk2(s, s);
        const ulonglong2* w3 = reinterpret_cast<const ulonglong2*>(c_w + 2960 + j * 16);
        #pragma unroll
        for (int r = 0; r < 4; ++r) {
            ulonglong2 w = w3[r];
            acc3[2 * r + 0] = ffma2(p, w.x, acc3[2 * r + 0]);
            acc3[2 * r + 1] = ffma2(p, w.y, acc3[2 * r + 1]);
        }
    }
    #pragma unroll
    for (int t = 0; t < 8; ++t) acc3[t] = relu2(acc3[t]);   // sel_out pairs

    // gating: per hidden neuron m, consume concat = [sel_out(16), sum_other(16)]
    float q0 = 0.0f, q1 = 0.0f;
    #pragma unroll 4
    for (int m = 0; m < 32; ++m) {
        ull a = 0ull;
        const ulonglong2* wg = reinterpret_cast<const ulonglong2*>(c_w + 3488 + m * 32);
        #pragma unroll
        for (int q = 0; q < 4; ++q) {
            ulonglong2 w = wg[q];
            a = ffma2(acc3[2 * q + 0], w.x, a);
            a = ffma2(acc3[2 * q + 1], w.y, a);
        }
        #pragma unroll
        for (int q = 0; q < 4; ++q) {
            ulonglong2 w = wg[4 + q];
            a = ffma2(so_p[2 * q + 0], w.x, a);
            a = ffma2(so_p[2 * q + 1], w.y, a);
        }
        float g = relu_(hadd2(a) + c_w[4512 + m]);
        q0 = fmaf(g, c_w[4544 + 2 * m + 0], q0);
        q1 = fmaf(g, c_w[4544 + 2 * m + 1], q1);
    }

    int act = (int)xs.w;
    act = act < 0 ? 0 : (act > 1 ? 1 : act);
    out_q[row] = act ? (q1 + c_w[4609]) : (q0 + c_w[4608]);
}

extern "C" void kernel_launch(void* const* d_in, const int* in_sizes, int n_in,
                              void* d_out, int out_size)
{
    (void)in_sizes; (void)n_in; (void)out_size;

    pack_kernel<<<1, 256>>>(
        (const float*)d_in[2],  (const float*)d_in[3],
        (const float*)d_in[4],  (const float*)d_in[5],
        (const float*)d_in[6],  (const float*)d_in[7],
        (const float*)d_in[8],  (const float*)d_in[9],
        (const float*)d_in[10], (const float*)d_in[11],
        (const float*)d_in[12], (const float*)d_in[13],
        (const float*)d_in[14], (const float*)d_in[15],
        (const float*)d_in[16], (const float*)d_in[17]);

    void* dst = nullptr;
    void* src = nullptr;
    cudaGetSymbolAddress(&dst, c_w);
    cudaGetSymbolAddress(&src, g_blob);
    cudaMemcpyAsync(dst, src, CW_TOTAL * sizeof(float),
                    cudaMemcpyDeviceToDevice, 0);

    // Kernel A: 65536 rows; 8 warps x 2 rows = 16 rows/block -> 4096 blocks
    mainmlp_kernel<<<4096, 256>>>((const float*)d_in[0], (const int*)d_in[1]);

    // Kernel B: lane = row -> 256 blocks x 256 threads
    tail_kernel<<<256, 256>>>((const float*)d_in[0], (const int*)d_in[1],
                              (float*)d_out);
}

// round 8
// speedup vs baseline: 2.0850x; 1.4337x over previous
#include <cuda_runtime.h>

#define FULL 0xffffffffu
typedef unsigned long long ull;
typedef unsigned int uint;

__device__ __forceinline__ float relu_(float v) { return fmaxf(v, 0.0f); }

__device__ __forceinline__ ull ffma2(ull a, ull b, ull c) {
    ull d; asm("fma.rn.f32x2 %0, %1, %2, %3;" : "=l"(d) : "l"(a), "l"(b), "l"(c)); return d;
}
__device__ __forceinline__ ull fadd2(ull a, ull b) {
    ull d; asm("add.rn.f32x2 %0, %1, %2;" : "=l"(d) : "l"(a), "l"(b)); return d;
}
__device__ __forceinline__ ull pk2(float lo, float hi) {
    ull r; asm("mov.b64 %0, {%1, %2};" : "=l"(r) : "f"(lo), "f"(hi)); return r;
}
__device__ __forceinline__ void upk2(ull v, float& lo, float& hi) {
    asm("mov.b64 {%0, %1}, %2;" : "=f"(lo), "=f"(hi) : "l"(v));
}
__device__ __forceinline__ ull relu2(ull v) {
    float lo, hi; upk2(v, lo, hi);
    return pk2(fmaxf(lo, 0.0f), fmaxf(hi, 0.0f));
}
__device__ __forceinline__ float hadd2(ull v) {
    float lo, hi; upk2(v, lo, hi); return lo + hi;
}

// bf16x2 split: hi = rn(e), lo = rn(e - hi). Element e0 -> lower 16 bits.
__device__ __forceinline__ void splitpair(float e0, float e1, uint& hi, uint& lo) {
    uint h;
    asm("cvt.rn.bf16x2.f32 %0, %1, %2;" : "=r"(h) : "f"(e1), "f"(e0));
    float h0 = __uint_as_float(h << 16);
    float h1 = __uint_as_float(h & 0xffff0000u);
    asm("cvt.rn.bf16x2.f32 %0, %1, %2;" : "=r"(lo) : "f"(e1 - h1), "f"(e0 - h0));
    hi = h;
}

// m16n8k16 bf16 MMA, fp32 accumulate in-place.
__device__ __forceinline__ void mma_bf16(float4& d, uint a0, uint a1, uint a2, uint a3,
                                         uint b0, uint b1) {
    asm volatile(
        "mma.sync.aligned.m16n8k16.row.col.f32.bf16.bf16.f32 "
        "{%0,%1,%2,%3}, {%4,%5,%6,%7}, {%8,%9}, {%0,%1,%2,%3};"
        : "+f"(d.x), "+f"(d.y), "+f"(d.z), "+f"(d.w)
        : "r"(a0), "r"(a1), "r"(a2), "r"(a3), "r"(b0), "r"(b1));
}

// ---------------- constant blob (tail weights; layout as round 7) ----------------
#define CW_TOTAL 4624
__constant__ __align__(16) float c_w[CW_TOTAL];
__device__   __align__(16) float g_blob[CW_TOTAL];

#define NROWS 65536
__device__ __align__(16) ull g_sum[NROWS * 8];

__global__ void pack_kernel(const float* __restrict__ oW1, const float* __restrict__ ob1,
                            const float* __restrict__ oW2, const float* __restrict__ ob2,
                            const float* __restrict__ oW3, const float* __restrict__ ob3,
                            const float* __restrict__ sW1, const float* __restrict__ sb1,
                            const float* __restrict__ sW2, const float* __restrict__ sb2,
                            const float* __restrict__ sW3, const float* __restrict__ sb3,
                            const float* __restrict__ gW1, const float* __restrict__ gb1,
                            const float* __restrict__ gW2, const float* __restrict__ gb2)
{
    int t = threadIdx.x;
    if (t < 128) {
        int tp = t >> 3, d = (t >> 1) & 3, e = t & 1;
        g_blob[t]        = oW1[d * 32 + 2 * tp + e];
        g_blob[1744 + t] = sW1[d * 32 + 2 * tp + e];
    }
    if (t < 32) {
        g_blob[128 + t]  = ob1[t];
        g_blob[1184 + t] = ob2[t];
        g_blob[1872 + t] = sb1[t];
        g_blob[2928 + t] = sb2[t];
        g_blob[4512 + t] = gb1[t];
    }
    for (int idx = t; idx < 1024; idx += 256) {
        int j = idx >> 5, i = idx & 31;
        g_blob[160  + j * 32 + i] = oW2[i * 32 + j];
        g_blob[1904 + j * 32 + i] = sW2[i * 32 + j];
        g_blob[3488 + j * 32 + i] = gW1[i * 32 + j];
    }
    for (int idx = t; idx < 512; idx += 256) {
        g_blob[1216 + idx] = oW3[idx];
        g_blob[2960 + idx] = sW3[idx];
    }
    if (t < 16) { g_blob[1728 + t] = ob3[t]; g_blob[3472 + t] = sb3[t]; }
    if (t >= 64 && t < 128) g_blob[4544 + t - 64] = gW2[t - 64];
    if (t >= 128 && t < 130) g_blob[4608 + t - 128] = gb2[t - 128];
}

// ---------------- Kernel A: other-agent MLP on the TENSOR pipe ----------------
// Persistent warps; 1 warp = 1 batch row (32 samples) per iteration.
// Split-bf16 (AhBh + AlBh + AhBl) -> fp32-accurate to ~2^-17.
// D-fragment of layer L == A-fragment of layer L+1 => per-lane relu+pack only.
__global__ __launch_bounds__(128, 2)
void hmma_kernel(const float* __restrict__ x,
                 const int*   __restrict__ selp,
                 const float* __restrict__ oW1, const float* __restrict__ ob1,
                 const float* __restrict__ oW2, const float* __restrict__ ob2,
                 const float* __restrict__ oW3, const float* __restrict__ ob3)
{
    const int lane  = threadIdx.x & 31;
    const int warp  = threadIdx.x >> 5;
    const int gwarp = blockIdx.x * 4 + warp;      // 0..4095
    const int g  = lane >> 2;                      // 0..7
    const int tc = lane & 3;                       // 0..3
    const int sel = selp[0];
    const uint Z = 0u;

    // ---- B fragments (loaded once per persistent warp) ----
    // G1: W1 is [4][32]; K padded to 16 -> rows k>=4 are zero (b1 reg = Z).
    uint B1h[4], B1l[4];
    #pragma unroll
    for (int n = 0; n < 4; ++n) {
        float wa = 0.0f, wb = 0.0f;
        if (tc < 2) {
            wa = oW1[(2 * tc) * 32 + 8 * n + g];
            wb = oW1[(2 * tc + 1) * 32 + 8 * n + g];
        }
        splitpair(wa, wb, B1h[n], B1l[n]);
    }
    // G2: W2 [32][32] row-major (k = input i, col = output j).
    uint B2h[4][2][2], B2l[4][2][2];
    #pragma unroll
    for (int n = 0; n < 4; ++n) {
        #pragma unroll
        for (int ks = 0; ks < 2; ++ks) {
            int c  = 8 * n + g;
            int k0 = 16 * ks + 2 * tc;
            splitpair(oW2[k0 * 32 + c],       oW2[(k0 + 1) * 32 + c], B2h[n][ks][0], B2l[n][ks][0]);
            splitpair(oW2[(k0 + 8) * 32 + c], oW2[(k0 + 9) * 32 + c], B2h[n][ks][1], B2l[n][ks][1]);
        }
    }
    // G3: W3 [32][16] row-major (k = input j, col = output).
    uint B3h[2][2][2], B3l[2][2][2];
    #pragma unroll
    for (int n = 0; n < 2; ++n) {
        #pragma unroll
        for (int ks = 0; ks < 2; ++ks) {
            int c  = 8 * n + g;
            int k0 = 16 * ks + 2 * tc;
            splitpair(oW3[k0 * 16 + c],       oW3[(k0 + 1) * 16 + c], B3h[n][ks][0], B3l[n][ks][0]);
            splitpair(oW3[(k0 + 8) * 16 + c], oW3[(k0 + 9) * 16 + c], B3h[n][ks][1], B3l[n][ks][1]);
        }
    }
    // Bias fragments: cols (8n + 2tc, 8n + 2tc + 1).
    float2 bz1[4], bz2[4], bz3[2];
    #pragma unroll
    for (int n = 0; n < 4; ++n) {
        bz1[n] = *reinterpret_cast<const float2*>(ob1 + 8 * n + 2 * tc);
        bz2[n] = *reinterpret_cast<const float2*>(ob2 + 8 * n + 2 * tc);
    }
    #pragma unroll
    for (int n = 0; n < 2; ++n)
        bz3[n] = *reinterpret_cast<const float2*>(ob3 + 8 * n + 2 * tc);

    // ---- persistent row loop: 16 rows per warp ----
    for (int it = 0; it < 16; ++it) {
        const int row = gwarp * 16 + it;
        const float* xr = x + (size_t)row * 128;

        // ---------- G1: X(32x4, pad K=16) @ W1 -> D1(32x32) ----------
        float4 D1[2][4];
        #pragma unroll
        for (int m = 0; m < 2; ++m) {
            // a0: sample m*16+g, cols 2tc..2tc+1 (tc>=2 lanes carry junk x B=0)
            float2 xa = *reinterpret_cast<const float2*>(xr + (m * 16 + g) * 4 + (tc & 1) * 2);
            float2 xb = *reinterpret_cast<const float2*>(xr + (m * 16 + 8 + g) * 4 + (tc & 1) * 2);
            uint a0h, a0l, a1h, a1l;
            splitpair(xa.x, xa.y, a0h, a0l);
            splitpair(xb.x, xb.y, a1h, a1l);
            #pragma unroll
            for (int n = 0; n < 4; ++n) {
                D1[m][n] = make_float4(bz1[n].x, bz1[n].y, bz1[n].x, bz1[n].y);
                mma_bf16(D1[m][n], a0h, a1h, a0h, a1h, B1h[n], Z);
                mma_bf16(D1[m][n], a0l, a1l, a0l, a1l, B1h[n], Z);
                mma_bf16(D1[m][n], a0h, a1h, a0h, a1h, B1l[n], Z);
            }
        }

        // ---------- G2: relu(D1) @ W2 -> D2(32x32) ----------
        float4 D2[2][4];
        #pragma unroll
        for (int m = 0; m < 2; ++m)
            #pragma unroll
            for (int n = 0; n < 4; ++n)
                D2[m][n] = make_float4(bz2[n].x, bz2[n].y, bz2[n].x, bz2[n].y);
        #pragma unroll
        for (int m = 0; m < 2; ++m) {
            #pragma unroll
            for (int ks = 0; ks < 2; ++ks) {
                float4 t0 = D1[m][2 * ks];
                float4 t1 = D1[m][2 * ks + 1];
                uint A0h, A0l, A1h, A1l, A2h, A2l, A3h, A3l;
                splitpair(relu_(t0.x), relu_(t0.y), A0h, A0l);
                splitpair(relu_(t0.z), relu_(t0.w), A1h, A1l);
                splitpair(relu_(t1.x), relu_(t1.y), A2h, A2l);
                splitpair(relu_(t1.z), relu_(t1.w), A3h, A3l);
                #pragma unroll
                for (int n = 0; n < 4; ++n) {
                    mma_bf16(D2[m][n], A0h, A1h, A2h, A3h, B2h[n][ks][0], B2h[n][ks][1]);
                    mma_bf16(D2[m][n], A0l, A1l, A2l, A3l, B2h[n][ks][0], B2h[n][ks][1]);
                    mma_bf16(D2[m][n], A0h, A1h, A2h, A3h, B2l[n][ks][0], B2l[n][ks][1]);
                }
            }
        }

        // ---------- G3: relu(D2) @ W3 -> D3(32x16) ----------
        float4 D3[2][2];
        #pragma unroll
        for (int m = 0; m < 2; ++m)
            #pragma unroll
            for (int n = 0; n < 2; ++n)
                D3[m][n] = make_float4(bz3[n].x, bz3[n].y, bz3[n].x, bz3[n].y);
        #pragma unroll
        for (int m = 0; m < 2; ++m) {
            #pragma unroll
            for (int ks = 0; ks < 2; ++ks) {
                float4 t0 = D2[m][2 * ks];
                float4 t1 = D2[m][2 * ks + 1];
                uint A0h, A0l, A1h, A1l, A2h, A2l, A3h, A3l;
                splitpair(relu_(t0.x), relu_(t0.y), A0h, A0l);
                splitpair(relu_(t0.z), relu_(t0.w), A1h, A1l);
                splitpair(relu_(t1.x), relu_(t1.y), A2h, A2l);
                splitpair(relu_(t1.z), relu_(t1.w), A3h, A3l);
                #pragma unroll
                for (int n = 0; n < 2; ++n) {
                    mma_bf16(D3[m][n], A0h, A1h, A2h, A3h, B3h[n][ks][0], B3h[n][ks][1]);
                    mma_bf16(D3[m][n], A0l, A1l, A2l, A3l, B3h[n][ks][0], B3h[n][ks][1]);
                    mma_bf16(D3[m][n], A0h, A1h, A2h, A3h, B3l[n][ks][0], B3l[n][ks][1]);
                }
            }
        }

        // ---------- epilogue: relu, mask selected agent, sum over samples ----------
        float v00 = 0.f, v01 = 0.f, v10 = 0.f, v11 = 0.f;
        #pragma unroll
        for (int m = 0; m < 2; ++m) {
            float mk0 = (m * 16 + g == sel) ? 0.0f : 1.0f;       // rows g
            float mk1 = (m * 16 + 8 + g == sel) ? 0.0f : 1.0f;   // rows g+8
            v00 += relu_(D3[m][0].x) * mk0 + relu_(D3[m][0].z) * mk1;
            v01 += relu_(D3[m][0].y) * mk0 + relu_(D3[m][0].w) * mk1;
            v10 += relu_(D3[m][1].x) * mk0 + relu_(D3[m][1].z) * mk1;
            v11 += relu_(D3[m][1].y) * mk0 + relu_(D3[m][1].w) * mk1;
        }
        ull p0 = pk2(v00, v01);
        ull p1 = pk2(v10, v11);
        #pragma unroll
        for (int off = 4; off < 32; off <<= 1) {    // reduce over g (lanes tc, tc+4, ...)
            p0 = fadd2(p0, __shfl_xor_sync(FULL, p0, off));
            p1 = fadd2(p1, __shfl_xor_sync(FULL, p1, off));
        }
        if (lane < 4) {
            g_sum[(size_t)row * 8 + tc]     = p0;   // cols 2tc, 2tc+1
            g_sum[(size_t)row * 8 + 4 + tc] = p1;   // cols 8+2tc, 8+2tc+1
        }
    }
}

// ---------------- Kernel B: tail (unchanged from round 7) ----------------
__global__ __launch_bounds__(256)
void tail_kernel(const float* __restrict__ x,
                 const int*   __restrict__ selp,
                 float* __restrict__ out_q)
{
    const int row = blockIdx.x * 256 + threadIdx.x;
    const int sel = selp[0];

    const float4 xs = reinterpret_cast<const float4*>(x)[row * 32 + sel];

    ull so_p[8];
    {
        const ulonglong2* src = reinterpret_cast<const ulonglong2*>(g_sum + (size_t)row * 8);
        #pragma unroll
        for (int r = 0; r < 4; ++r) {
            ulonglong2 v = src[r];
            so_p[2 * r + 0] = v.x;
            so_p[2 * r + 1] = v.y;
        }
    }

    ull xd0 = pk2(xs.x, xs.x), xd1 = pk2(xs.y, xs.y);
    ull xd2 = pk2(xs.z, xs.z), xd3 = pk2(xs.w, xs.w);
    ull h1[16];
    {
        const ulonglong2* w1 = reinterpret_cast<const ulonglong2*>(c_w + 1744);
        const ull* b1 = reinterpret_cast<const ull*>(c_w + 1872);
        #pragma unroll
        for (int t = 0; t < 16; ++t) {
            ulonglong2 wA = w1[2 * t + 0];
            ulonglong2 wB = w1[2 * t + 1];
            ull a = ffma2(xd0, wA.x, b1[t]);
            a = ffma2(xd1, wA.y, a);
            a = ffma2(xd2, wB.x, a);
            a = ffma2(xd3, wB.y, a);
            h1[t] = relu2(a);
        }
    }

    ull acc3[8];
    {
        const ull* b3 = reinterpret_cast<const ull*>(c_w + 3472);
        #pragma unroll
        for (int t = 0; t < 8; ++t) acc3[t] = b3[t];
    }
    #pragma unroll 4
    for (int j = 0; j < 32; ++j) {
        ull a = 0ull;
        const ulonglong2* w2 = reinterpret_cast<const ulonglong2*>(c_w + 1904 + j * 32);
        #pragma unroll
        for (int q = 0; q < 8; ++q) {
            ulonglong2 w = w2[q];
            a = ffma2(h1[2 * q + 0], w.x, a);
            a = ffma2(h1[2 * q + 1], w.y, a);
        }
        float s = relu_(hadd2(a) + c_w[2928 + j]);
        ull p = pk2(s, s);
        const ulonglong2* w3 = reinterpret_cast<const ulonglong2*>(c_w + 2960 + j * 16);
        #pragma unroll
        for (int r = 0; r < 4; ++r) {
            ulonglong2 w = w3[r];
            acc3[2 * r + 0] = ffma2(p, w.x, acc3[2 * r + 0]);
            acc3[2 * r + 1] = ffma2(p, w.y, acc3[2 * r + 1]);
        }
    }
    #pragma unroll
    for (int t = 0; t < 8; ++t) acc3[t] = relu2(acc3[t]);

    float q0 = 0.0f, q1 = 0.0f;
    #pragma unroll 4
    for (int m = 0; m < 32; ++m) {
        ull a = 0ull;
        const ulonglong2* wg = reinterpret_cast<const ulonglong2*>(c_w + 3488 + m * 32);
        #pragma unroll
        for (int q = 0; q < 4; ++q) {
            ulonglong2 w = wg[q];
            a = ffma2(acc3[2 * q + 0], w.x, a);
            a = ffma2(acc3[2 * q + 1], w.y, a);
        }
        #pragma unroll
        for (int q = 0; q < 4; ++q) {
            ulonglong2 w = wg[4 + q];
            a = ffma2(so_p[2 * q + 0], w.x, a);
            a = ffma2(so_p[2 * q + 1], w.y, a);
        }
        float gg = relu_(hadd2(a) + c_w[4512 + m]);
        q0 = fmaf(gg, c_w[4544 + 2 * m + 0], q0);
        q1 = fmaf(gg, c_w[4544 + 2 * m + 1], q1);
    }

    int act = (int)xs.w;
    act = act < 0 ? 0 : (act > 1 ? 1 : act);
    out_q[row] = act ? (q1 + c_w[4609]) : (q0 + c_w[4608]);
}

extern "C" void kernel_launch(void* const* d_in, const int* in_sizes, int n_in,
                              void* d_out, int out_size)
{
    (void)in_sizes; (void)n_in; (void)out_size;

    pack_kernel<<<1, 256>>>(
        (const float*)d_in[2],  (const float*)d_in[3],
        (const float*)d_in[4],  (const float*)d_in[5],
        (const float*)d_in[6],  (const float*)d_in[7],
        (const float*)d_in[8],  (const float*)d_in[9],
        (const float*)d_in[10], (const float*)d_in[11],
        (const float*)d_in[12], (const float*)d_in[13],
        (const float*)d_in[14], (const float*)d_in[15],
        (const float*)d_in[16], (const float*)d_in[17]);

    void* dst = nullptr;
    void* src = nullptr;
    cudaGetSymbolAddress(&dst, c_w);
    cudaGetSymbolAddress(&src, g_blob);
    cudaMemcpyAsync(dst, src, CW_TOTAL * sizeof(float),
                    cudaMemcpyDeviceToDevice, 0);

    // Kernel A (tensor pipe): 1024 blocks x 4 warps x 16 rows = 65536 rows
    hmma_kernel<<<1024, 128>>>(
        (const float*)d_in[0], (const int*)d_in[1],
        (const float*)d_in[2], (const float*)d_in[3],
        (const float*)d_in[4], (const float*)d_in[5],
        (const float*)d_in[6], (const float*)d_in[7]);

    // Kernel B: tail
    tail_kernel<<<256, 256>>>((const float*)d_in[0], (const int*)d_in[1],
                              (float*)d_out);
}

// round 9
// speedup vs baseline: 2.2152x; 1.0624x over previous
#include <cuda_runtime.h>

#define FULL 0xffffffffu
typedef unsigned long long ull;
typedef unsigned int uint;

__device__ __forceinline__ float relu_(float v) { return fmaxf(v, 0.0f); }

__device__ __forceinline__ ull ffma2(ull a, ull b, ull c) {
    ull d; asm("fma.rn.f32x2 %0, %1, %2, %3;" : "=l"(d) : "l"(a), "l"(b), "l"(c)); return d;
}
__device__ __forceinline__ ull fadd2(ull a, ull b) {
    ull d; asm("add.rn.f32x2 %0, %1, %2;" : "=l"(d) : "l"(a), "l"(b)); return d;
}
__device__ __forceinline__ ull pk2(float lo, float hi) {
    ull r; asm("mov.b64 %0, {%1, %2};" : "=l"(r) : "f"(lo), "f"(hi)); return r;
}
__device__ __forceinline__ void upk2(ull v, float& lo, float& hi) {
    asm("mov.b64 {%0, %1}, %2;" : "=f"(lo), "=f"(hi) : "l"(v));
}
__device__ __forceinline__ ull relu2(ull v) {
    float lo, hi; upk2(v, lo, hi);
    return pk2(fmaxf(lo, 0.0f), fmaxf(hi, 0.0f));
}
__device__ __forceinline__ float hadd2(ull v) {
    float lo, hi; upk2(v, lo, hi); return lo + hi;
}

// bf16x2 split: hi = rn(e), lo = rn(e - hi). Element e0 -> lower 16 bits.
__device__ __forceinline__ void splitpair(float e0, float e1, uint& hi, uint& lo) {
    uint h;
    asm("cvt.rn.bf16x2.f32 %0, %1, %2;" : "=r"(h) : "f"(e1), "f"(e0));
    float h0 = __uint_as_float(h << 16);
    float h1 = __uint_as_float(h & 0xffff0000u);
    asm("cvt.rn.bf16x2.f32 %0, %1, %2;" : "=r"(lo) : "f"(e1 - h1), "f"(e0 - h0));
    hi = h;
}

// m16n8k16 bf16 MMA, fp32 accumulate in-place.
__device__ __forceinline__ void mma_bf16(float4& d, uint a0, uint a1, uint a2, uint a3,
                                         uint b0, uint b1) {
    asm volatile(
        "mma.sync.aligned.m16n8k16.row.col.f32.bf16.bf16.f32 "
        "{%0,%1,%2,%3}, {%4,%5,%6,%7}, {%8,%9}, {%0,%1,%2,%3};"
        : "+f"(d.x), "+f"(d.y), "+f"(d.z), "+f"(d.w)
        : "r"(a0), "r"(a1), "r"(a2), "r"(a3), "r"(b0), "r"(b1));
}

// ---------------- constant blob (tail weights; layout as round 7/8) ----------------
#define CW_TOTAL 4624
__constant__ __align__(16) float c_w[CW_TOTAL];
__device__   __align__(16) float g_blob[CW_TOTAL];

#define NROWS 65536
__device__ __align__(16) ull g_sum[NROWS * 8];

// Parallelized over 8 blocks (round-8's single block was 7.8us of pure latency).
__global__ void pack_kernel(const float* __restrict__ oW1, const float* __restrict__ ob1,
                            const float* __restrict__ oW2, const float* __restrict__ ob2,
                            const float* __restrict__ oW3, const float* __restrict__ ob3,
                            const float* __restrict__ sW1, const float* __restrict__ sb1,
                            const float* __restrict__ sW2, const float* __restrict__ sb2,
                            const float* __restrict__ sW3, const float* __restrict__ sb3,
                            const float* __restrict__ gW1, const float* __restrict__ gb1,
                            const float* __restrict__ gW2, const float* __restrict__ gb2)
{
    const int gt = blockIdx.x * 256 + threadIdx.x;   // 0..2047
    if (gt < 128) {
        int tp = gt >> 3, d = (gt >> 1) & 3, e = gt & 1;
        g_blob[gt]        = oW1[d * 32 + 2 * tp + e];
        g_blob[1744 + gt] = sW1[d * 32 + 2 * tp + e];
    }
    if (gt >= 128 && gt < 160) {
        int t = gt - 128;
        g_blob[128 + t]  = ob1[t];
        g_blob[1184 + t] = ob2[t];
        g_blob[1872 + t] = sb1[t];
        g_blob[2928 + t] = sb2[t];
        g_blob[4512 + t] = gb1[t];
    }
    if (gt >= 160 && gt < 176) { g_blob[1728 + gt - 160] = ob3[gt - 160]; }
    if (gt >= 176 && gt < 192) { g_blob[3472 + gt - 176] = sb3[gt - 176]; }
    if (gt >= 192 && gt < 256) { g_blob[4544 + gt - 192] = gW2[gt - 192]; }
    if (gt >= 256 && gt < 258) { g_blob[4608 + gt - 256] = gb2[gt - 256]; }
    if (gt < 1024) {
        int j = gt >> 5, i = gt & 31;
        g_blob[160  + j * 32 + i] = oW2[i * 32 + j];
        g_blob[1904 + j * 32 + i] = sW2[i * 32 + j];
        g_blob[3488 + j * 32 + i] = gW1[i * 32 + j];
    }
    if (gt >= 1024 && gt < 1536) {
        int idx = gt - 1024;
        g_blob[1216 + idx] = oW3[idx];
        g_blob[2960 + idx] = sW3[idx];
    }
}

// ---------------- Kernel A: other-agent MLP on the TENSOR pipe ----------------
// Persistent warps; 1 warp = 1 batch row (32 samples) per iteration.
// Register-liveness fused: D1 chunk -> D2 immediately; G3+epilogue per m.
// 12 warps/SM via __launch_bounds__(128,3).
__global__ __launch_bounds__(128, 3)
void hmma_kernel(const float* __restrict__ x,
                 const int*   __restrict__ selp,
                 const float* __restrict__ oW1, const float* __restrict__ ob1,
                 const float* __restrict__ oW2, const float* __restrict__ ob2,
                 const float* __restrict__ oW3, const float* __restrict__ ob3)
{
    const int lane  = threadIdx.x & 31;
    const int warp  = threadIdx.x >> 5;
    const int gwarp = blockIdx.x * 4 + warp;      // 0..4095
    const int g  = lane >> 2;                      // 0..7
    const int tc = lane & 3;                       // 0..3
    const int sel = selp[0];
    const uint Z = 0u;

    // ---- B fragments (loaded once per persistent warp) ----
    uint B1h[4], B1l[4];
    #pragma unroll
    for (int n = 0; n < 4; ++n) {
        float wa = 0.0f, wb = 0.0f;
        if (tc < 2) {
            wa = oW1[(2 * tc) * 32 + 8 * n + g];
            wb = oW1[(2 * tc + 1) * 32 + 8 * n + g];
        }
        splitpair(wa, wb, B1h[n], B1l[n]);
    }
    uint B2h[4][2][2], B2l[4][2][2];
    #pragma unroll
    for (int n = 0; n < 4; ++n) {
        #pragma unroll
        for (int ks = 0; ks < 2; ++ks) {
            int c  = 8 * n + g;
            int k0 = 16 * ks + 2 * tc;
            splitpair(oW2[k0 * 32 + c],       oW2[(k0 + 1) * 32 + c], B2h[n][ks][0], B2l[n][ks][0]);
            splitpair(oW2[(k0 + 8) * 32 + c], oW2[(k0 + 9) * 32 + c], B2h[n][ks][1], B2l[n][ks][1]);
        }
    }
    uint B3h[2][2][2], B3l[2][2][2];
    #pragma unroll
    for (int n = 0; n < 2; ++n) {
        #pragma unroll
        for (int ks = 0; ks < 2; ++ks) {
            int c  = 8 * n + g;
            int k0 = 16 * ks + 2 * tc;
            splitpair(oW3[k0 * 16 + c],       oW3[(k0 + 1) * 16 + c], B3h[n][ks][0], B3l[n][ks][0]);
            splitpair(oW3[(k0 + 8) * 16 + c], oW3[(k0 + 9) * 16 + c], B3h[n][ks][1], B3l[n][ks][1]);
        }
    }
    float2 bz1[4], bz2[4], bz3[2];
    #pragma unroll
    for (int n = 0; n < 4; ++n) {
        bz1[n] = *reinterpret_cast<const float2*>(ob1 + 8 * n + 2 * tc);
        bz2[n] = *reinterpret_cast<const float2*>(ob2 + 8 * n + 2 * tc);
    }
    #pragma unroll
    for (int n = 0; n < 2; ++n)
        bz3[n] = *reinterpret_cast<const float2*>(ob3 + 8 * n + 2 * tc);

    // per-lane x offsets (within a row of 128 floats)
    const int offA0 = (g) * 4 + (tc & 1) * 2;
    const int offB0 = (8 + g) * 4 + (tc & 1) * 2;
    const int offA1 = (16 + g) * 4 + (tc & 1) * 2;
    const int offB1 = (24 + g) * 4 + (tc & 1) * 2;

    const float* xr = x + (size_t)(gwarp * 16) * 128;

    // prefetch first row
    float2 nA0 = *reinterpret_cast<const float2*>(xr + offA0);
    float2 nB0 = *reinterpret_cast<const float2*>(xr + offB0);
    float2 nA1 = *reinterpret_cast<const float2*>(xr + offA1);
    float2 nB1 = *reinterpret_cast<const float2*>(xr + offB1);

    // ---- persistent row loop: 16 rows per warp ----
    for (int it = 0; it < 16; ++it) {
        const int row = gwarp * 16 + it;
        float2 cA[2] = { nA0, nA1 };
        float2 cB[2] = { nB0, nB1 };
        if (it < 15) {   // software pipeline: issue next row's loads now
            const float* xn = xr + 128;
            nA0 = *reinterpret_cast<const float2*>(xn + offA0);
            nB0 = *reinterpret_cast<const float2*>(xn + offB0);
            nA1 = *reinterpret_cast<const float2*>(xn + offA1);
            nB1 = *reinterpret_cast<const float2*>(xn + offB1);
        }
        xr += 128;

        float v00 = 0.f, v01 = 0.f, v10 = 0.f, v11 = 0.f;

        #pragma unroll
        for (int m = 0; m < 2; ++m) {
            // x splits for this m
            uint a0h, a0l, a1h, a1l;
            splitpair(cA[m].x, cA[m].y, a0h, a0l);
            splitpair(cB[m].x, cB[m].y, a1h, a1l);

            // D2 init with bias
            float4 D2[4];
            #pragma unroll
            for (int n = 0; n < 4; ++n)
                D2[n] = make_float4(bz2[n].x, bz2[n].y, bz2[n].x, bz2[n].y);

            // G1 chunk -> G2 accumulate, per ks (D1 chunk dies immediately)
            #pragma unroll
            for (int ks = 0; ks < 2; ++ks) {
                float4 D1c[2];
                #pragma unroll
                for (int nn = 0; nn < 2; ++nn) {
                    int n = 2 * ks + nn;
                    D1c[nn] = make_float4(bz1[n].x, bz1[n].y, bz1[n].x, bz1[n].y);
                    mma_bf16(D1c[nn], a0h, a1h, a0h, a1h, B1h[n], Z);
                    mma_bf16(D1c[nn], a0l, a1l, a0l, a1l, B1h[n], Z);
                    mma_bf16(D1c[nn], a0h, a1h, a0h, a1h, B1l[n], Z);
                }
                uint A0h, A0l, A1h, A1l, A2h, A2l, A3h, A3l;
                splitpair(relu_(D1c[0].x), relu_(D1c[0].y), A0h, A0l);
                splitpair(relu_(D1c[0].z), relu_(D1c[0].w), A1h, A1l);
                splitpair(relu_(D1c[1].x), relu_(D1c[1].y), A2h, A2l);
                splitpair(relu_(D1c[1].z), relu_(D1c[1].w), A3h, A3l);
                #pragma unroll
                for (int n = 0; n < 4; ++n) {
                    mma_bf16(D2[n], A0h, A1h, A2h, A3h, B2h[n][ks][0], B2h[n][ks][1]);
                    mma_bf16(D2[n], A0l, A1l, A2l, A3l, B2h[n][ks][0], B2h[n][ks][1]);
                    mma_bf16(D2[n], A0h, A1h, A2h, A3h, B2l[n][ks][0], B2l[n][ks][1]);
                }
            }

            // G3 for this m (D3 chunk local, dies in epilogue)
            float4 D3[2];
            #pragma unroll
            for (int n = 0; n < 2; ++n)
                D3[n] = make_float4(bz3[n].x, bz3[n].y, bz3[n].x, bz3[n].y);
            #pragma unroll
            for (int ks = 0; ks < 2; ++ks) {
                uint A0h, A0l, A1h, A1l, A2h, A2l, A3h, A3l;
                splitpair(relu_(D2[2 * ks].x), relu_(D2[2 * ks].y), A0h, A0l);
                splitpair(relu_(D2[2 * ks].z), relu_(D2[2 * ks].w), A1h, A1l);
                splitpair(relu_(D2[2 * ks + 1].x), relu_(D2[2 * ks + 1].y), A2h, A2l);
                splitpair(relu_(D2[2 * ks + 1].z), relu_(D2[2 * ks + 1].w), A3h, A3l);
                #pragma unroll
                for (int n = 0; n < 2; ++n) {
                    mma_bf16(D3[n], A0h, A1h, A2h, A3h, B3h[n][ks][0], B3h[n][ks][1]);
                    mma_bf16(D3[n], A0l, A1l, A2l, A3l, B3h[n][ks][0], B3h[n][ks][1]);
                    mma_bf16(D3[n], A0h, A1h, A2h, A3h, B3l[n][ks][0], B3l[n][ks][1]);
                }
            }

            // epilogue for this m: relu, mask selected agent, accumulate
            float mk0 = (m * 16 + g == sel) ? 0.0f : 1.0f;
            float mk1 = (m * 16 + 8 + g == sel) ? 0.0f : 1.0f;
            v00 += relu_(D3[0].x) * mk0 + relu_(D3[0].z) * mk1;
            v01 += relu_(D3[0].y) * mk0 + relu_(D3[0].w) * mk1;
            v10 += relu_(D3[1].x) * mk0 + relu_(D3[1].z) * mk1;
            v11 += relu_(D3[1].y) * mk0 + relu_(D3[1].w) * mk1;
        }

        ull p0 = pk2(v00, v01);
        ull p1 = pk2(v10, v11);
        #pragma unroll
        for (int off = 4; off < 32; off <<= 1) {
            p0 = fadd2(p0, __shfl_xor_sync(FULL, p0, off));
            p1 = fadd2(p1, __shfl_xor_sync(FULL, p1, off));
        }
        if (lane < 4) {
            g_sum[(size_t)row * 8 + tc]     = p0;
            g_sum[(size_t)row * 8 + 4 + tc] = p1;
        }
    }
}

// ---------------- Kernel B: tail (unchanged) ----------------
__global__ __launch_bounds__(256)
void tail_kernel(const float* __restrict__ x,
                 const int*   __restrict__ selp,
                 float* __restrict__ out_q)
{
    const int row = blockIdx.x * 256 + threadIdx.x;
    const int sel = selp[0];

    const float4 xs = reinterpret_cast<const float4*>(x)[row * 32 + sel];

    ull so_p[8];
    {
        const ulonglong2* src = reinterpret_cast<const ulonglong2*>(g_sum + (size_t)row * 8);
        #pragma unroll
        for (int r = 0; r < 4; ++r) {
            ulonglong2 v = src[r];
            so_p[2 * r + 0] = v.x;
            so_p[2 * r + 1] = v.y;
        }
    }

    ull xd0 = pk2(xs.x, xs.x), xd1 = pk2(xs.y, xs.y);
    ull xd2 = pk2(xs.z, xs.z), xd3 = pk2(xs.w, xs.w);
    ull h1[16];
    {
        const ulonglong2* w1 = reinterpret_cast<const ulonglong2*>(c_w + 1744);
        const ull* b1 = reinterpret_cast<const ull*>(c_w + 1872);
        #pragma unroll
        for (int t = 0; t < 16; ++t) {
            ulonglong2 wA = w1[2 * t + 0];
            ulonglong2 wB = w1[2 * t + 1];
            ull a = ffma2(xd0, wA.x, b1[t]);
            a = ffma2(xd1, wA.y, a);
            a = ffma2(xd2, wB.x, a);
            a = ffma2(xd3, wB.y, a);
            h1[t] = relu2(a);
        }
    }

    ull acc3[8];
    {
        const ull* b3 = reinterpret_cast<const ull*>(c_w + 3472);
        #pragma unroll
        for (int t = 0; t < 8; ++t) acc3[t] = b3[t];
    }
    #pragma unroll 4
    for (int j = 0; j < 32; ++j) {
        ull a = 0ull;
        const ulonglong2* w2 = reinterpret_cast<const ulonglong2*>(c_w + 1904 + j * 32);
        #pragma unroll
        for (int q = 0; q < 8; ++q) {
            ulonglong2 w = w2[q];
            a = ffma2(h1[2 * q + 0], w.x, a);
            a = ffma2(h1[2 * q + 1], w.y, a);
        }
        float s = relu_(hadd2(a) + c_w[2928 + j]);
        ull p = pk2(s, s);
        const ulonglong2* w3 = reinterpret_cast<const ulonglong2*>(c_w + 2960 + j * 16);
        #pragma unroll
        for (int r = 0; r < 4; ++r) {
            ulonglong2 w = w3[r];
            acc3[2 * r + 0] = ffma2(p, w.x, acc3[2 * r + 0]);
            acc3[2 * r + 1] = ffma2(p, w.y, acc3[2 * r + 1]);
        }
    }
    #pragma unroll
    for (int t = 0; t < 8; ++t) acc3[t] = relu2(acc3[t]);

    float q0 = 0.0f, q1 = 0.0f;
    #pragma unroll 4
    for (int m = 0; m < 32; ++m) {
        ull a = 0ull;
        const ulonglong2* wg = reinterpret_cast<const ulonglong2*>(c_w + 3488 + m * 32);
        #pragma unroll
        for (int q = 0; q < 4; ++q) {
            ulonglong2 w = wg[q];
            a = ffma2(acc3[2 * q + 0], w.x, a);
            a = ffma2(acc3[2 * q + 1], w.y, a);
        }
        #pragma unroll
        for (int q = 0; q < 4; ++q) {
            ulonglong2 w = wg[4 + q];
            a = ffma2(so_p[2 * q + 0], w.x, a);
            a = ffma2(so_p[2 * q + 1], w.y, a);
        }
        float gg = relu_(hadd2(a) + c_w[4512 + m]);
        q0 = fmaf(gg, c_w[4544 + 2 * m + 0], q0);
        q1 = fmaf(gg, c_w[4544 + 2 * m + 1], q1);
    }

    int act = (int)xs.w;
    act = act < 0 ? 0 : (act > 1 ? 1 : act);
    out_q[row] = act ? (q1 + c_w[4609]) : (q0 + c_w[4608]);
}

extern "C" void kernel_launch(void* const* d_in, const int* in_sizes, int n_in,
                              void* d_out, int out_size)
{
    (void)in_sizes; (void)n_in; (void)out_size;

    pack_kernel<<<8, 256>>>(
        (const float*)d_in[2],  (const float*)d_in[3],
        (const float*)d_in[4],  (const float*)d_in[5],
        (const float*)d_in[6],  (const float*)d_in[7],
        (const float*)d_in[8],  (const float*)d_in[9],
        (const float*)d_in[10], (const float*)d_in[11],
        (const float*)d_in[12], (const float*)d_in[13],
        (const float*)d_in[14], (const float*)d_in[15],
        (const float*)d_in[16], (const float*)d_in[17]);

    void* dst = nullptr;
    void* src = nullptr;
    cudaGetSymbolAddress(&dst, c_w);
    cudaGetSymbolAddress(&src, g_blob);
    cudaMemcpyAsync(dst, src, CW_TOTAL * sizeof(float),
                    cudaMemcpyDeviceToDevice, 0);

    // Kernel A (tensor pipe): 1024 blocks x 4 warps x 16 rows = 65536 rows
    hmma_kernel<<<1024, 128>>>(
        (const float*)d_in[0], (const int*)d_in[1],
        (const float*)d_in[2], (const float*)d_in[3],
        (const float*)d_in[4], (const float*)d_in[5],
        (const float*)d_in[6], (const float*)d_in[7]);

    // Kernel B: tail
    tail_kernel<<<256, 256>>>((const float*)d_in[0], (const int*)d_in[1],
                              (float*)d_out);
}

// round 10
// speedup vs baseline: 2.8974x; 1.3079x over previous
#include <cuda_runtime.h>
#include <cuda_fp16.h>

#define FULL 0xffffffffu
typedef unsigned long long ull;
typedef unsigned int uint;

__device__ __forceinline__ float relu_(float v) { return fmaxf(v, 0.0f); }

__device__ __forceinline__ ull ffma2(ull a, ull b, ull c) {
    ull d; asm("fma.rn.f32x2 %0, %1, %2, %3;" : "=l"(d) : "l"(a), "l"(b), "l"(c)); return d;
}
__device__ __forceinline__ ull fadd2(ull a, ull b) {
    ull d; asm("add.rn.f32x2 %0, %1, %2;" : "=l"(d) : "l"(a), "l"(b)); return d;
}
__device__ __forceinline__ ull pk2(float lo, float hi) {
    ull r; asm("mov.b64 %0, {%1, %2};" : "=l"(r) : "f"(lo), "f"(hi)); return r;
}
__device__ __forceinline__ void upk2(ull v, float& lo, float& hi) {
    asm("mov.b64 {%0, %1}, %2;" : "=f"(lo), "=f"(hi) : "l"(v));
}
__device__ __forceinline__ ull relu2(ull v) {
    float lo, hi; upk2(v, lo, hi);
    return pk2(fmaxf(lo, 0.0f), fmaxf(hi, 0.0f));
}
__device__ __forceinline__ float hadd2(ull v) {
    float lo, hi; upk2(v, lo, hi); return lo + hi;
}

// fp16x2 pack (e0 -> lower 16 bits)
__device__ __forceinline__ uint pack_f16(float e0, float e1) {
    __half2 h = __floats2half2_rn(e0, e1);
    return *reinterpret_cast<uint*>(&h);
}
// fp16x2 split: hi = rn(e), lo = rn(e - hi).  A = Ah + Al exact to ~2^-22.
__device__ __forceinline__ void splitpair_f16(float e0, float e1, uint& hi, uint& lo) {
    __half2 h = __floats2half2_rn(e0, e1);
    hi = *reinterpret_cast<uint*>(&h);
    float2 hf = __half22float2(h);
    __half2 l = __floats2half2_rn(e0 - hf.x, e1 - hf.y);
    lo = *reinterpret_cast<uint*>(&l);
}

// m16n8k16 fp16 MMA, fp32 accumulate in-place.
__device__ __forceinline__ void mma_f16(float4& d, uint a0, uint a1, uint a2, uint a3,
                                        uint b0, uint b1) {
    asm volatile(
        "mma.sync.aligned.m16n8k16.row.col.f32.f16.f16.f32 "
        "{%0,%1,%2,%3}, {%4,%5,%6,%7}, {%8,%9}, {%0,%1,%2,%3};"
        : "+f"(d.x), "+f"(d.y), "+f"(d.z), "+f"(d.w)
        : "r"(a0), "r"(a1), "r"(a2), "r"(a3), "r"(b0), "r"(b1));
}

// ---------------- constant blob (tail weights; layout as round 7/8/9) ----------------
#define CW_TOTAL 4624
__constant__ __align__(16) float c_w[CW_TOTAL];
__device__   __align__(16) float g_blob[CW_TOTAL];

#define NROWS 65536
__device__ __align__(16) ull g_sum[NROWS * 8];

__global__ void pack_kernel(const float* __restrict__ oW1, const float* __restrict__ ob1,
                            const float* __restrict__ oW2, const float* __restrict__ ob2,
                            const float* __restrict__ oW3, const float* __restrict__ ob3,
                            const float* __restrict__ sW1, const float* __restrict__ sb1,
                            const float* __restrict__ sW2, const float* __restrict__ sb2,
                            const float* __restrict__ sW3, const float* __restrict__ sb3,
                            const float* __restrict__ gW1, const float* __restrict__ gb1,
                            const float* __restrict__ gW2, const float* __restrict__ gb2)
{
    const int gt = blockIdx.x * 256 + threadIdx.x;   // 0..2047
    if (gt < 128) {
        int tp = gt >> 3, d = (gt >> 1) & 3, e = gt & 1;
        g_blob[gt]        = oW1[d * 32 + 2 * tp + e];
        g_blob[1744 + gt] = sW1[d * 32 + 2 * tp + e];
    }
    if (gt >= 128 && gt < 160) {
        int t = gt - 128;
        g_blob[128 + t]  = ob1[t];
        g_blob[1184 + t] = ob2[t];
        g_blob[1872 + t] = sb1[t];
        g_blob[2928 + t] = sb2[t];
        g_blob[4512 + t] = gb1[t];
    }
    if (gt >= 160 && gt < 176) { g_blob[1728 + gt - 160] = ob3[gt - 160]; }
    if (gt >= 176 && gt < 192) { g_blob[3472 + gt - 176] = sb3[gt - 176]; }
    if (gt >= 192 && gt < 256) { g_blob[4544 + gt - 192] = gW2[gt - 192]; }
    if (gt >= 256 && gt < 258) { g_blob[4608 + gt - 256] = gb2[gt - 256]; }
    if (gt < 1024) {
        int j = gt >> 5, i = gt & 31;
        g_blob[160  + j * 32 + i] = oW2[i * 32 + j];
        g_blob[1904 + j * 32 + i] = sW2[i * 32 + j];
        g_blob[3488 + j * 32 + i] = gW1[i * 32 + j];
    }
    if (gt >= 1024 && gt < 1536) {
        int idx = gt - 1024;
        g_blob[1216 + idx] = oW3[idx];
        g_blob[2960 + idx] = sW3[idx];
    }
}

// ---------------- Kernel A: other-agent MLP on the TENSOR pipe (fp16, 2-term) -------
// Persistent warps; 1 warp = 1 batch row (32 samples) per iteration.
// A = Ah + Al split (exact); B single fp16 (err ~2^-12).
// G1 K-stacked: xh at k0-3, xl at k8-11 vs stacked W1h -> 1 MMA per n-tile.
__global__ __launch_bounds__(128, 3)
void hmma_kernel(const float* __restrict__ x,
                 const int*   __restrict__ selp,
                 const float* __restrict__ oW1, const float* __restrict__ ob1,
                 const float* __restrict__ oW2, const float* __restrict__ ob2,
                 const float* __restrict__ oW3, const float* __restrict__ ob3)
{
    const int lane  = threadIdx.x & 31;
    const int warp  = threadIdx.x >> 5;
    const int gwarp = blockIdx.x * 4 + warp;      // 0..4095
    const int g  = lane >> 2;                      // 0..7
    const int tc = lane & 3;                       // 0..3
    const int sel = selp[0];

    // ---- B fragments (single fp16, loaded once per persistent warp) ----
    // G1: b0 covers k=2tc..2tc+1 (W1 rows), b1 covers k=2tc+8..2tc+9 which maps
    // back to the SAME W1 rows (K-stacked low half) -> b1 = b0; zero for tc>=2.
    uint B1[4];
    #pragma unroll
    for (int n = 0; n < 4; ++n) {
        float wa = 0.0f, wb = 0.0f;
        if (tc < 2) {
            wa = oW1[(2 * tc) * 32 + 8 * n + g];
            wb = oW1[(2 * tc + 1) * 32 + 8 * n + g];
        }
        B1[n] = pack_f16(wa, wb);
    }
    uint B2[4][2][2];
    #pragma unroll
    for (int n = 0; n < 4; ++n) {
        #pragma unroll
        for (int ks = 0; ks < 2; ++ks) {
            int c  = 8 * n + g;
            int k0 = 16 * ks + 2 * tc;
            B2[n][ks][0] = pack_f16(oW2[k0 * 32 + c],       oW2[(k0 + 1) * 32 + c]);
            B2[n][ks][1] = pack_f16(oW2[(k0 + 8) * 32 + c], oW2[(k0 + 9) * 32 + c]);
        }
    }
    uint B3[2][2][2];
    #pragma unroll
    for (int n = 0; n < 2; ++n) {
        #pragma unroll
        for (int ks = 0; ks < 2; ++ks) {
            int c  = 8 * n + g;
            int k0 = 16 * ks + 2 * tc;
            B3[n][ks][0] = pack_f16(oW3[k0 * 16 + c],       oW3[(k0 + 1) * 16 + c]);
            B3[n][ks][1] = pack_f16(oW3[(k0 + 8) * 16 + c], oW3[(k0 + 9) * 16 + c]);
        }
    }
    float2 bz1[4], bz2[4], bz3[2];
    #pragma unroll
    for (int n = 0; n < 4; ++n) {
        bz1[n] = *reinterpret_cast<const float2*>(ob1 + 8 * n + 2 * tc);
        bz2[n] = *reinterpret_cast<const float2*>(ob2 + 8 * n + 2 * tc);
    }
    #pragma unroll
    for (int n = 0; n < 2; ++n)
        bz3[n] = *reinterpret_cast<const float2*>(ob3 + 8 * n + 2 * tc);

    // per-lane x offsets (within a row of 128 floats)
    const int offA0 = (g) * 4 + (tc & 1) * 2;
    const int offB0 = (8 + g) * 4 + (tc & 1) * 2;
    const int offA1 = (16 + g) * 4 + (tc & 1) * 2;
    const int offB1 = (24 + g) * 4 + (tc & 1) * 2;

    const float* xr = x + (size_t)(gwarp * 16) * 128;

    // prefetch first row
    float2 nA0 = *reinterpret_cast<const float2*>(xr + offA0);
    float2 nB0 = *reinterpret_cast<const float2*>(xr + offB0);
    float2 nA1 = *reinterpret_cast<const float2*>(xr + offA1);
    float2 nB1 = *reinterpret_cast<const float2*>(xr + offB1);

    // ---- persistent row loop: 16 rows per warp ----
    for (int it = 0; it < 16; ++it) {
        const int row = gwarp * 16 + it;
        float2 cA[2] = { nA0, nA1 };
        float2 cB[2] = { nB0, nB1 };
        if (it < 15) {
            const float* xn = xr + 128;
            nA0 = *reinterpret_cast<const float2*>(xn + offA0);
            nB0 = *reinterpret_cast<const float2*>(xn + offB0);
            nA1 = *reinterpret_cast<const float2*>(xn + offA1);
            nB1 = *reinterpret_cast<const float2*>(xn + offB1);
        }
        xr += 128;

        float v00 = 0.f, v01 = 0.f, v10 = 0.f, v11 = 0.f;

        #pragma unroll
        for (int m = 0; m < 2; ++m) {
            // x splits (A exact via 2-term; B already carries the zero-mask for tc>=2)
            uint a0h, a0l, a1h, a1l;
            splitpair_f16(cA[m].x, cA[m].y, a0h, a0l);
            splitpair_f16(cB[m].x, cB[m].y, a1h, a1l);

            // ---- G1: one K-stacked MMA per n-tile (xh at k0-3, xl at k8-11) ----
            float4 D1[4];
            #pragma unroll
            for (int n = 0; n < 4; ++n) {
                D1[n] = make_float4(bz1[n].x, bz1[n].y, bz1[n].x, bz1[n].y);
                mma_f16(D1[n], a0h, a1h, a0l, a1l, B1[n], B1[n]);
            }

            // ---- G2: relu(D1) -> split A; 2 MMAs (h,l) per n per ks ----
            float4 D2[4];
            #pragma unroll
            for (int n = 0; n < 4; ++n)
                D2[n] = make_float4(bz2[n].x, bz2[n].y, bz2[n].x, bz2[n].y);
            #pragma unroll
            for (int ks = 0; ks < 2; ++ks) {
                uint A0h, A0l, A1h, A1l, A2h, A2l, A3h, A3l;
                splitpair_f16(relu_(D1[2 * ks].x), relu_(D1[2 * ks].y), A0h, A0l);
                splitpair_f16(relu_(D1[2 * ks].z), relu_(D1[2 * ks].w), A1h, A1l);
                splitpair_f16(relu_(D1[2 * ks + 1].x), relu_(D1[2 * ks + 1].y), A2h, A2l);
                splitpair_f16(relu_(D1[2 * ks + 1].z), relu_(D1[2 * ks + 1].w), A3h, A3l);
                #pragma unroll
                for (int n = 0; n < 4; ++n) {
                    mma_f16(D2[n], A0h, A1h, A2h, A3h, B2[n][ks][0], B2[n][ks][1]);
                    mma_f16(D2[n], A0l, A1l, A2l, A3l, B2[n][ks][0], B2[n][ks][1]);
                }
            }

            // ---- G3 ----
            float4 D3[2];
            #pragma unroll
            for (int n = 0; n < 2; ++n)
                D3[n] = make_float4(bz3[n].x, bz3[n].y, bz3[n].x, bz3[n].y);
            #pragma unroll
            for (int ks = 0; ks < 2; ++ks) {
                uint A0h, A0l, A1h, A1l, A2h, A2l, A3h, A3l;
                splitpair_f16(relu_(D2[2 * ks].x), relu_(D2[2 * ks].y), A0h, A0l);
                splitpair_f16(relu_(D2[2 * ks].z), relu_(D2[2 * ks].w), A1h, A1l);
                splitpair_f16(relu_(D2[2 * ks + 1].x), relu_(D2[2 * ks + 1].y), A2h, A2l);
                splitpair_f16(relu_(D2[2 * ks + 1].z), relu_(D2[2 * ks + 1].w), A3h, A3l);
                #pragma unroll
                for (int n = 0; n < 2; ++n) {
                    mma_f16(D3[n], A0h, A1h, A2h, A3h, B3[n][ks][0], B3[n][ks][1]);
                    mma_f16(D3[n], A0l, A1l, A2l, A3l, B3[n][ks][0], B3[n][ks][1]);
                }
            }

            // epilogue for this m: relu, mask selected agent, accumulate
            float mk0 = (m * 16 + g == sel) ? 0.0f : 1.0f;
            float mk1 = (m * 16 + 8 + g == sel) ? 0.0f : 1.0f;
            v00 += relu_(D3[0].x) * mk0 + relu_(D3[0].z) * mk1;
            v01 += relu_(D3[0].y) * mk0 + relu_(D3[0].w) * mk1;
            v10 += relu_(D3[1].x) * mk0 + relu_(D3[1].z) * mk1;
            v11 += relu_(D3[1].y) * mk0 + relu_(D3[1].w) * mk1;
        }

        ull p0 = pk2(v00, v01);
        ull p1 = pk2(v10, v11);
        #pragma unroll
        for (int off = 4; off < 32; off <<= 1) {
            p0 = fadd2(p0, __shfl_xor_sync(FULL, p0, off));
            p1 = fadd2(p1, __shfl_xor_sync(FULL, p1, off));
        }
        if (lane < 4) {
            g_sum[(size_t)row * 8 + tc]     = p0;
            g_sum[(size_t)row * 8 + 4 + tc] = p1;
        }
    }
}

// ---------------- Kernel B: tail (unchanged, full fp32) ----------------
__global__ __launch_bounds__(256)
void tail_kernel(const float* __restrict__ x,
                 const int*   __restrict__ selp,
                 float* __restrict__ out_q)
{
    const int row = blockIdx.x * 256 + threadIdx.x;
    const int sel = selp[0];

    const float4 xs = reinterpret_cast<const float4*>(x)[row * 32 + sel];

    ull so_p[8];
    {
        const ulonglong2* src = reinterpret_cast<const ulonglong2*>(g_sum + (size_t)row * 8);
        #pragma unroll
        for (int r = 0; r < 4; ++r) {
            ulonglong2 v = src[r];
            so_p[2 * r + 0] = v.x;
            so_p[2 * r + 1] = v.y;
        }
    }

    ull xd0 = pk2(xs.x, xs.x), xd1 = pk2(xs.y, xs.y);
    ull xd2 = pk2(xs.z, xs.z), xd3 = pk2(xs.w, xs.w);
    ull h1[16];
    {
        const ulonglong2* w1 = reinterpret_cast<const ulonglong2*>(c_w + 1744);
        const ull* b1 = reinterpret_cast<const ull*>(c_w + 1872);
        #pragma unroll
        for (int t = 0; t < 16; ++t) {
            ulonglong2 wA = w1[2 * t + 0];
            ulonglong2 wB = w1[2 * t + 1];
            ull a = ffma2(xd0, wA.x, b1[t]);
            a = ffma2(xd1, wA.y, a);
            a = ffma2(xd2, wB.x, a);
            a = ffma2(xd3, wB.y, a);
            h1[t] = relu2(a);
        }
    }

    ull acc3[8];
    {
        const ull* b3 = reinterpret_cast<const ull*>(c_w + 3472);
        #pragma unroll
        for (int t = 0; t < 8; ++t) acc3[t] = b3[t];
    }
    #pragma unroll 4
    for (int j = 0; j < 32; ++j) {
        ull a = 0ull;
        const ulonglong2* w2 = reinterpret_cast<const ulonglong2*>(c_w + 1904 + j * 32);
        #pragma unroll
        for (int q = 0; q < 8; ++q) {
            ulonglong2 w = w2[q];
            a = ffma2(h1[2 * q + 0], w.x, a);
            a = ffma2(h1[2 * q + 1], w.y, a);
        }
        float s = relu_(hadd2(a) + c_w[2928 + j]);
        ull p = pk2(s, s);
        const ulonglong2* w3 = reinterpret_cast<const ulonglong2*>(c_w + 2960 + j * 16);
        #pragma unroll
        for (int r = 0; r < 4; ++r) {
            ulonglong2 w = w3[r];
            acc3[2 * r + 0] = ffma2(p, w.x, acc3[2 * r + 0]);
            acc3[2 * r + 1] = ffma2(p, w.y, acc3[2 * r + 1]);
        }
    }
    #pragma unroll
    for (int t = 0; t < 8; ++t) acc3[t] = relu2(acc3[t]);

    float q0 = 0.0f, q1 = 0.0f;
    #pragma unroll 4
    for (int m = 0; m < 32; ++m) {
        ull a = 0ull;
        const ulonglong2* wg = reinterpret_cast<const ulonglong2*>(c_w + 3488 + m * 32);
        #pragma unroll
        for (int q = 0; q < 4; ++q) {
            ulonglong2 w = wg[q];
            a = ffma2(acc3[2 * q + 0], w.x, a);
            a = ffma2(acc3[2 * q + 1], w.y, a);
        }
        #pragma unroll
        for (int q = 0; q < 4; ++q) {
            ulonglong2 w = wg[4 + q];
            a = ffma2(so_p[2 * q + 0], w.x, a);
            a = ffma2(so_p[2 * q + 1], w.y, a);
        }
        float gg = relu_(hadd2(a) + c_w[4512 + m]);
        q0 = fmaf(gg, c_w[4544 + 2 * m + 0], q0);
        q1 = fmaf(gg, c_w[4544 + 2 * m + 1], q1);
    }

    int act = (int)xs.w;
    act = act < 0 ? 0 : (act > 1 ? 1 : act);
    out_q[row] = act ? (q1 + c_w[4609]) : (q0 + c_w[4608]);
}

extern "C" void kernel_launch(void* const* d_in, const int* in_sizes, int n_in,
                              void* d_out, int out_size)
{
    (void)in_sizes; (void)n_in; (void)out_size;

    pack_kernel<<<8, 256>>>(
        (const float*)d_in[2],  (const float*)d_in[3],
        (const float*)d_in[4],  (const float*)d_in[5],
        (const float*)d_in[6],  (const float*)d_in[7],
        (const float*)d_in[8],  (const float*)d_in[9],
        (const float*)d_in[10], (const float*)d_in[11],
        (const float*)d_in[12], (const float*)d_in[13],
        (const float*)d_in[14], (const float*)d_in[15],
        (const float*)d_in[16], (const float*)d_in[17]);

    void* dst = nullptr;
    void* src = nullptr;
    cudaGetSymbolAddress(&dst, c_w);
    cudaGetSymbolAddress(&src, g_blob);
    cudaMemcpyAsync(dst, src, CW_TOTAL * sizeof(float),
                    cudaMemcpyDeviceToDevice, 0);

    // Kernel A (tensor pipe): 1024 blocks x 4 warps x 16 rows = 65536 rows
    hmma_kernel<<<1024, 128>>>(
        (const float*)d_in[0], (const int*)d_in[1],
        (const float*)d_in[2], (const float*)d_in[3],
        (const float*)d_in[4], (const float*)d_in[5],
        (const float*)d_in[6], (const float*)d_in[7]);

    // Kernel B: tail
    tail_kernel<<<256, 256>>>((const float*)d_in[0], (const int*)d_in[1],
                              (float*)d_out);
}

// round 11
// speedup vs baseline: 3.7337x; 1.2887x over previous
#include <cuda_runtime.h>
#include <cuda_fp16.h>

#define FULL 0xffffffffu
typedef unsigned long long ull;
typedef unsigned int uint;

__device__ __forceinline__ float relu_(float v) { return fmaxf(v, 0.0f); }

__device__ __forceinline__ ull ffma2(ull a, ull b, ull c) {
    ull d; asm("fma.rn.f32x2 %0, %1, %2, %3;" : "=l"(d) : "l"(a), "l"(b), "l"(c)); return d;
}
__device__ __forceinline__ ull fadd2(ull a, ull b) {
    ull d; asm("add.rn.f32x2 %0, %1, %2;" : "=l"(d) : "l"(a), "l"(b)); return d;
}
__device__ __forceinline__ ull pk2(float lo, float hi) {
    ull r; asm("mov.b64 %0, {%1, %2};" : "=l"(r) : "f"(lo), "f"(hi)); return r;
}
__device__ __forceinline__ void upk2(ull v, float& lo, float& hi) {
    asm("mov.b64 {%0, %1}, %2;" : "=f"(lo), "=f"(hi) : "l"(v));
}
__device__ __forceinline__ ull relu2(ull v) {
    float lo, hi; upk2(v, lo, hi);
    return pk2(fmaxf(lo, 0.0f), fmaxf(hi, 0.0f));
}
__device__ __forceinline__ float hadd2(ull v) {
    float lo, hi; upk2(v, lo, hi); return lo + hi;
}

// fp16x2 pack (e0 -> lower 16 bits)
__device__ __forceinline__ uint pack_f16(float e0, float e1) {
    __half2 h = __floats2half2_rn(e0, e1);
    return *reinterpret_cast<uint*>(&h);
}
// fp16x2 split: hi = rn(e), lo = rn(e - hi).  A = Ah + Al exact to ~2^-22.
__device__ __forceinline__ void splitpair_f16(float e0, float e1, uint& hi, uint& lo) {
    __half2 h = __floats2half2_rn(e0, e1);
    hi = *reinterpret_cast<uint*>(&h);
    float2 hf = __half22float2(h);
    __half2 l = __floats2half2_rn(e0 - hf.x, e1 - hf.y);
    lo = *reinterpret_cast<uint*>(&l);
}

// m16n8k16 fp16 MMA, fp32 accumulate in-place.
__device__ __forceinline__ void mma_f16(float4& d, uint a0, uint a1, uint a2, uint a3,
                                        uint b0, uint b1) {
    asm volatile(
        "mma.sync.aligned.m16n8k16.row.col.f32.f16.f16.f32 "
        "{%0,%1,%2,%3}, {%4,%5,%6,%7}, {%8,%9}, {%0,%1,%2,%3};"
        : "+f"(d.x), "+f"(d.y), "+f"(d.z), "+f"(d.w)
        : "r"(a0), "r"(a1), "r"(a2), "r"(a3), "r"(b0), "r"(b1));
}

// ---------------- constant blob (tail weights; layout as rounds 7-10) ----------------
#define CW_TOTAL 4624
__constant__ __align__(16) float c_w[CW_TOTAL];
__device__   __align__(16) float g_blob[CW_TOTAL];

#define NROWS 65536
__device__ __align__(16) ull g_sum[NROWS * 8];

__global__ void pack_kernel(const float* __restrict__ oW1, const float* __restrict__ ob1,
                            const float* __restrict__ oW2, const float* __restrict__ ob2,
                            const float* __restrict__ oW3, const float* __restrict__ ob3,
                            const float* __restrict__ sW1, const float* __restrict__ sb1,
                            const float* __restrict__ sW2, const float* __restrict__ sb2,
                            const float* __restrict__ sW3, const float* __restrict__ sb3,
                            const float* __restrict__ gW1, const float* __restrict__ gb1,
                            const float* __restrict__ gW2, const float* __restrict__ gb2)
{
    const int gt = blockIdx.x * 256 + threadIdx.x;   // 0..2047
    if (gt < 128) {
        int tp = gt >> 3, d = (gt >> 1) & 3, e = gt & 1;
        g_blob[gt]        = oW1[d * 32 + 2 * tp + e];
        g_blob[1744 + gt] = sW1[d * 32 + 2 * tp + e];
    }
    if (gt >= 128 && gt < 160) {
        int t = gt - 128;
        g_blob[128 + t]  = ob1[t];
        g_blob[1184 + t] = ob2[t];
        g_blob[1872 + t] = sb1[t];
        g_blob[2928 + t] = sb2[t];
        g_blob[4512 + t] = gb1[t];
    }
    if (gt >= 160 && gt < 176) { g_blob[1728 + gt - 160] = ob3[gt - 160]; }
    if (gt >= 176 && gt < 192) { g_blob[3472 + gt - 176] = sb3[gt - 176]; }
    if (gt >= 192 && gt < 256) { g_blob[4544 + gt - 192] = gW2[gt - 192]; }
    if (gt >= 256 && gt < 258) { g_blob[4608 + gt - 256] = gb2[gt - 256]; }
    if (gt < 1024) {
        int j = gt >> 5, i = gt & 31;
        g_blob[160  + j * 32 + i] = oW2[i * 32 + j];
        g_blob[1904 + j * 32 + i] = sW2[i * 32 + j];
        g_blob[3488 + j * 32 + i] = gW1[i * 32 + j];
    }
    if (gt >= 1024 && gt < 1536) {
        int idx = gt - 1024;
        g_blob[1216 + idx] = oW3[idx];
        g_blob[2960 + idx] = sW3[idx];
    }
}

// ---------------- Kernel A: other-agent MLP on TENSOR pipe (fp16, 32 MMA/row) -------
// G1: K-stacked exact A-split (8 MMAs). G2/G3: single-fp16 A (16 + 8 MMAs).
__global__ __launch_bounds__(128, 3)
void hmma_kernel(const float* __restrict__ x,
                 const int*   __restrict__ selp,
                 const float* __restrict__ oW1, const float* __restrict__ ob1,
                 const float* __restrict__ oW2, const float* __restrict__ ob2,
                 const float* __restrict__ oW3, const float* __restrict__ ob3)
{
    const int lane  = threadIdx.x & 31;
    const int warp  = threadIdx.x >> 5;
    const int gwarp = blockIdx.x * 4 + warp;      // 0..4095
    const int g  = lane >> 2;                      // 0..7
    const int tc = lane & 3;                       // 0..3
    const int sel = selp[0];

    // ---- B fragments (single fp16) ----
    uint B1[4];
    #pragma unroll
    for (int n = 0; n < 4; ++n) {
        float wa = 0.0f, wb = 0.0f;
        if (tc < 2) {
            wa = oW1[(2 * tc) * 32 + 8 * n + g];
            wb = oW1[(2 * tc + 1) * 32 + 8 * n + g];
        }
        B1[n] = pack_f16(wa, wb);
    }
    uint B2[4][2][2];
    #pragma unroll
    for (int n = 0; n < 4; ++n) {
        #pragma unroll
        for (int ks = 0; ks < 2; ++ks) {
            int c  = 8 * n + g;
            int k0 = 16 * ks + 2 * tc;
            B2[n][ks][0] = pack_f16(oW2[k0 * 32 + c],       oW2[(k0 + 1) * 32 + c]);
            B2[n][ks][1] = pack_f16(oW2[(k0 + 8) * 32 + c], oW2[(k0 + 9) * 32 + c]);
        }
    }
    uint B3[2][2][2];
    #pragma unroll
    for (int n = 0; n < 2; ++n) {
        #pragma unroll
        for (int ks = 0; ks < 2; ++ks) {
            int c  = 8 * n + g;
            int k0 = 16 * ks + 2 * tc;
            B3[n][ks][0] = pack_f16(oW3[k0 * 16 + c],       oW3[(k0 + 1) * 16 + c]);
            B3[n][ks][1] = pack_f16(oW3[(k0 + 8) * 16 + c], oW3[(k0 + 9) * 16 + c]);
        }
    }
    float2 bz1[4], bz2[4], bz3[2];
    #pragma unroll
    for (int n = 0; n < 4; ++n) {
        bz1[n] = *reinterpret_cast<const float2*>(ob1 + 8 * n + 2 * tc);
        bz2[n] = *reinterpret_cast<const float2*>(ob2 + 8 * n + 2 * tc);
    }
    #pragma unroll
    for (int n = 0; n < 2; ++n)
        bz3[n] = *reinterpret_cast<const float2*>(ob3 + 8 * n + 2 * tc);

    // per-lane x offsets (within a row of 128 floats)
    const int offA0 = (g) * 4 + (tc & 1) * 2;
    const int offB0 = (8 + g) * 4 + (tc & 1) * 2;
    const int offA1 = (16 + g) * 4 + (tc & 1) * 2;
    const int offB1 = (24 + g) * 4 + (tc & 1) * 2;

    const float* xr = x + (size_t)(gwarp * 16) * 128;

    // prefetch first row
    float2 nA0 = *reinterpret_cast<const float2*>(xr + offA0);
    float2 nB0 = *reinterpret_cast<const float2*>(xr + offB0);
    float2 nA1 = *reinterpret_cast<const float2*>(xr + offA1);
    float2 nB1 = *reinterpret_cast<const float2*>(xr + offB1);

    // ---- persistent row loop: 16 rows per warp ----
    for (int it = 0; it < 16; ++it) {
        const int row = gwarp * 16 + it;
        float2 cA[2] = { nA0, nA1 };
        float2 cB[2] = { nB0, nB1 };
        if (it < 15) {
            const float* xn = xr + 128;
            nA0 = *reinterpret_cast<const float2*>(xn + offA0);
            nB0 = *reinterpret_cast<const float2*>(xn + offB0);
            nA1 = *reinterpret_cast<const float2*>(xn + offA1);
            nB1 = *reinterpret_cast<const float2*>(xn + offB1);
        }
        xr += 128;

        float v00 = 0.f, v01 = 0.f, v10 = 0.f, v11 = 0.f;

        #pragma unroll
        for (int m = 0; m < 2; ++m) {
            // exact x split feeds G1's K-stacked MMA (split is free precision)
            uint a0h, a0l, a1h, a1l;
            splitpair_f16(cA[m].x, cA[m].y, a0h, a0l);
            splitpair_f16(cB[m].x, cB[m].y, a1h, a1l);

            // ---- G1: one K-stacked MMA per n-tile ----
            float4 D1[4];
            #pragma unroll
            for (int n = 0; n < 4; ++n) {
                D1[n] = make_float4(bz1[n].x, bz1[n].y, bz1[n].x, bz1[n].y);
                mma_f16(D1[n], a0h, a1h, a0l, a1l, B1[n], B1[n]);
            }

            // ---- G2: relu(D1) single-fp16 A; 1 MMA per n per ks ----
            float4 D2[4];
            #pragma unroll
            for (int n = 0; n < 4; ++n)
                D2[n] = make_float4(bz2[n].x, bz2[n].y, bz2[n].x, bz2[n].y);
            #pragma unroll
            for (int ks = 0; ks < 2; ++ks) {
                uint A0 = pack_f16(relu_(D1[2 * ks].x),     relu_(D1[2 * ks].y));
                uint A1 = pack_f16(relu_(D1[2 * ks].z),     relu_(D1[2 * ks].w));
                uint A2 = pack_f16(relu_(D1[2 * ks + 1].x), relu_(D1[2 * ks + 1].y));
                uint A3 = pack_f16(relu_(D1[2 * ks + 1].z), relu_(D1[2 * ks + 1].w));
                #pragma unroll
                for (int n = 0; n < 4; ++n)
                    mma_f16(D2[n], A0, A1, A2, A3, B2[n][ks][0], B2[n][ks][1]);
            }

            // ---- G3: relu(D2) single-fp16 A ----
            float4 D3[2];
            #pragma unroll
            for (int n = 0; n < 2; ++n)
                D3[n] = make_float4(bz3[n].x, bz3[n].y, bz3[n].x, bz3[n].y);
            #pragma unroll
            for (int ks = 0; ks < 2; ++ks) {
                uint A0 = pack_f16(relu_(D2[2 * ks].x),     relu_(D2[2 * ks].y));
                uint A1 = pack_f16(relu_(D2[2 * ks].z),     relu_(D2[2 * ks].w));
                uint A2 = pack_f16(relu_(D2[2 * ks + 1].x), relu_(D2[2 * ks + 1].y));
                uint A3 = pack_f16(relu_(D2[2 * ks + 1].z), relu_(D2[2 * ks + 1].w));
                #pragma unroll
                for (int n = 0; n < 2; ++n)
                    mma_f16(D3[n], A0, A1, A2, A3, B3[n][ks][0], B3[n][ks][1]);
            }

            // epilogue: relu, mask selected agent, accumulate
            float mk0 = (m * 16 + g == sel) ? 0.0f : 1.0f;
            float mk1 = (m * 16 + 8 + g == sel) ? 0.0f : 1.0f;
            v00 += relu_(D3[0].x) * mk0 + relu_(D3[0].z) * mk1;
            v01 += relu_(D3[0].y) * mk0 + relu_(D3[0].w) * mk1;
            v10 += relu_(D3[1].x) * mk0 + relu_(D3[1].z) * mk1;
            v11 += relu_(D3[1].y) * mk0 + relu_(D3[1].w) * mk1;
        }

        ull p0 = pk2(v00, v01);
        ull p1 = pk2(v10, v11);
        #pragma unroll
        for (int off = 4; off < 32; off <<= 1) {
            p0 = fadd2(p0, __shfl_xor_sync(FULL, p0, off));
            p1 = fadd2(p1, __shfl_xor_sync(FULL, p1, off));
        }
        if (lane < 4) {
            g_sum[(size_t)row * 8 + tc]     = p0;
            g_sum[(size_t)row * 8 + 4 + tc] = p1;
        }
    }
}

// ---------------- Kernel B: tail (unchanged, full fp32) ----------------
__global__ __launch_bounds__(256)
void tail_kernel(const float* __restrict__ x,
                 const int*   __restrict__ selp,
                 float* __restrict__ out_q)
{
    const int row = blockIdx.x * 256 + threadIdx.x;
    const int sel = selp[0];

    const float4 xs = reinterpret_cast<const float4*>(x)[row * 32 + sel];

    ull so_p[8];
    {
        const ulonglong2* src = reinterpret_cast<const ulonglong2*>(g_sum + (size_t)row * 8);
        #pragma unroll
        for (int r = 0; r < 4; ++r) {
            ulonglong2 v = src[r];
            so_p[2 * r + 0] = v.x;
            so_p[2 * r + 1] = v.y;
        }
    }

    ull xd0 = pk2(xs.x, xs.x), xd1 = pk2(xs.y, xs.y);
    ull xd2 = pk2(xs.z, xs.z), xd3 = pk2(xs.w, xs.w);
    ull h1[16];
    {
        const ulonglong2* w1 = reinterpret_cast<const ulonglong2*>(c_w + 1744);
        const ull* b1 = reinterpret_cast<const ull*>(c_w + 1872);
        #pragma unroll
        for (int t = 0; t < 16; ++t) {
            ulonglong2 wA = w1[2 * t + 0];
            ulonglong2 wB = w1[2 * t + 1];
            ull a = ffma2(xd0, wA.x, b1[t]);
            a = ffma2(xd1, wA.y, a);
            a = ffma2(xd2, wB.x, a);
            a = ffma2(xd3, wB.y, a);
            h1[t] = relu2(a);
        }
    }

    ull acc3[8];
    {
        const ull* b3 = reinterpret_cast<const ull*>(c_w + 3472);
        #pragma unroll
        for (int t = 0; t < 8; ++t) acc3[t] = b3[t];
    }
    #pragma unroll 4
    for (int j = 0; j < 32; ++j) {
        ull a = 0ull;
        const ulonglong2* w2 = reinterpret_cast<const ulonglong2*>(c_w + 1904 + j * 32);
        #pragma unroll
        for (int q = 0; q < 8; ++q) {
            ulonglong2 w = w2[q];
            a = ffma2(h1[2 * q + 0], w.x, a);
            a = ffma2(h1[2 * q + 1], w.y, a);
        }
        float s = relu_(hadd2(a) + c_w[2928 + j]);
        ull p = pk2(s, s);
        const ulonglong2* w3 = reinterpret_cast<const ulonglong2*>(c_w + 2960 + j * 16);
        #pragma unroll
        for (int r = 0; r < 4; ++r) {
            ulonglong2 w = w3[r];
            acc3[2 * r + 0] = ffma2(p, w.x, acc3[2 * r + 0]);
            acc3[2 * r + 1] = ffma2(p, w.y, acc3[2 * r + 1]);
        }
    }
    #pragma unroll
    for (int t = 0; t < 8; ++t) acc3[t] = relu2(acc3[t]);

    float q0 = 0.0f, q1 = 0.0f;
    #pragma unroll 4
    for (int m = 0; m < 32; ++m) {
        ull a = 0ull;
        const ulonglong2* wg = reinterpret_cast<const ulonglong2*>(c_w + 3488 + m * 32);
        #pragma unroll
        for (int q = 0; q < 4; ++q) {
            ulonglong2 w = wg[q];
            a = ffma2(acc3[2 * q + 0], w.x, a);
            a = ffma2(acc3[2 * q + 1], w.y, a);
        }
        #pragma unroll
        for (int q = 0; q < 4; ++q) {
            ulonglong2 w = wg[4 + q];
            a = ffma2(so_p[2 * q + 0], w.x, a);
            a = ffma2(so_p[2 * q + 1], w.y, a);
        }
        float gg = relu_(hadd2(a) + c_w[4512 + m]);
        q0 = fmaf(gg, c_w[4544 + 2 * m + 0], q0);
        q1 = fmaf(gg, c_w[4544 + 2 * m + 1], q1);
    }

    int act = (int)xs.w;
    act = act < 0 ? 0 : (act > 1 ? 1 : act);
    out_q[row] = act ? (q1 + c_w[4609]) : (q0 + c_w[4608]);
}

extern "C" void kernel_launch(void* const* d_in, const int* in_sizes, int n_in,
                              void* d_out, int out_size)
{
    (void)in_sizes; (void)n_in; (void)out_size;

    // One-time side stream + events (host resources only, created outside capture
    // on the correctness call, reused during capture).
    static cudaStream_t s2 = nullptr;
    static cudaEvent_t evFork = nullptr, evJoin = nullptr;
    if (!s2) {
        cudaStreamCreateWithFlags(&s2, cudaStreamNonBlocking);
        cudaEventCreateWithFlags(&evFork, cudaEventDisableTiming);
        cudaEventCreateWithFlags(&evJoin, cudaEventDisableTiming);
    }

    void* dst = nullptr;
    void* src = nullptr;
    cudaGetSymbolAddress(&dst, c_w);
    cudaGetSymbolAddress(&src, g_blob);

    // Fork: pack + memcpy on s2, overlapped with hmma on the main stream.
    cudaEventRecord(evFork, 0);
    cudaStreamWaitEvent(s2, evFork, 0);

    pack_kernel<<<8, 256, 0, s2>>>(
        (const float*)d_in[2],  (const float*)d_in[3],
        (const float*)d_in[4],  (const float*)d_in[5],
        (const float*)d_in[6],  (const float*)d_in[7],
        (const float*)d_in[8],  (const float*)d_in[9],
        (const float*)d_in[10], (const float*)d_in[11],
        (const float*)d_in[12], (const float*)d_in[13],
        (const float*)d_in[14], (const float*)d_in[15],
        (const float*)d_in[16], (const float*)d_in[17]);
    cudaMemcpyAsync(dst, src, CW_TOTAL * sizeof(float),
                    cudaMemcpyDeviceToDevice, s2);
    cudaEventRecord(evJoin, s2);

    // Kernel A (tensor pipe) on the main stream, independent of c_w.
    hmma_kernel<<<1024, 128>>>(
        (const float*)d_in[0], (const int*)d_in[1],
        (const float*)d_in[2], (const float*)d_in[3],
        (const float*)d_in[4], (const float*)d_in[5],
        (const float*)d_in[6], (const float*)d_in[7]);

    // Join: tail needs both g_sum (main stream) and c_w (s2).
    cudaStreamWaitEvent(0, evJoin, 0);
    tail_kernel<<<256, 256>>>((const float*)d_in[0], (const int*)d_in[1],
                              (float*)d_out);
}

// round 12
// speedup vs baseline: 3.8053x; 1.0192x over previous
#include <cuda_runtime.h>
#include <cuda_fp16.h>

#define FULL 0xffffffffu
typedef unsigned long long ull;
typedef unsigned int uint;

__device__ __forceinline__ float relu_(float v) { return fmaxf(v, 0.0f); }

__device__ __forceinline__ ull ffma2(ull a, ull b, ull c) {
    ull d; asm("fma.rn.f32x2 %0, %1, %2, %3;" : "=l"(d) : "l"(a), "l"(b), "l"(c)); return d;
}
__device__ __forceinline__ ull fadd2(ull a, ull b) {
    ull d; asm("add.rn.f32x2 %0, %1, %2;" : "=l"(d) : "l"(a), "l"(b)); return d;
}
__device__ __forceinline__ ull pk2(float lo, float hi) {
    ull r; asm("mov.b64 %0, {%1, %2};" : "=l"(r) : "f"(lo), "f"(hi)); return r;
}
__device__ __forceinline__ void upk2(ull v, float& lo, float& hi) {
    asm("mov.b64 {%0, %1}, %2;" : "=f"(lo), "=f"(hi) : "l"(v));
}
__device__ __forceinline__ ull relu2(ull v) {
    float lo, hi; upk2(v, lo, hi);
    return pk2(fmaxf(lo, 0.0f), fmaxf(hi, 0.0f));
}
__device__ __forceinline__ float hadd2(ull v) {
    float lo, hi; upk2(v, lo, hi); return lo + hi;
}

// fp16x2 pack (e0 -> lower 16 bits)
__device__ __forceinline__ uint pack_f16(float e0, float e1) {
    __half2 h = __floats2half2_rn(e0, e1);
    return *reinterpret_cast<uint*>(&h);
}
// relu in the fp16x2 domain (sign-equivalent to relu-before-cvt)
__device__ __forceinline__ uint hrelu2(uint v) {
    uint r; asm("max.f16x2 %0, %1, %2;" : "=r"(r) : "r"(v), "r"(0u)); return r;
}
// fused pack + relu
__device__ __forceinline__ uint packrelu_f16(float e0, float e1) {
    return hrelu2(pack_f16(e0, e1));
}

// m16n8k16 fp16 MMA, fp32 accumulate in-place.
__device__ __forceinline__ void mma_f16(float4& d, uint a0, uint a1, uint a2, uint a3,
                                        uint b0, uint b1) {
    asm volatile(
        "mma.sync.aligned.m16n8k16.row.col.f32.f16.f16.f32 "
        "{%0,%1,%2,%3}, {%4,%5,%6,%7}, {%8,%9}, {%0,%1,%2,%3};"
        : "+f"(d.x), "+f"(d.y), "+f"(d.z), "+f"(d.w)
        : "r"(a0), "r"(a1), "r"(a2), "r"(a3), "r"(b0), "r"(b1));
}

// ---------------- constant blob (tail weights; layout as rounds 7-11) ----------------
#define CW_TOTAL 4624
__constant__ __align__(16) float c_w[CW_TOTAL];
__device__   __align__(16) float g_blob[CW_TOTAL];

#define NROWS 65536
__device__ __align__(16) ull g_sum[NROWS * 8];

__global__ void pack_kernel(const float* __restrict__ oW1, const float* __restrict__ ob1,
                            const float* __restrict__ oW2, const float* __restrict__ ob2,
                            const float* __restrict__ oW3, const float* __restrict__ ob3,
                            const float* __restrict__ sW1, const float* __restrict__ sb1,
                            const float* __restrict__ sW2, const float* __restrict__ sb2,
                            const float* __restrict__ sW3, const float* __restrict__ sb3,
                            const float* __restrict__ gW1, const float* __restrict__ gb1,
                            const float* __restrict__ gW2, const float* __restrict__ gb2)
{
    const int gt = blockIdx.x * 256 + threadIdx.x;   // 0..2047
    if (gt < 128) {
        int tp = gt >> 3, d = (gt >> 1) & 3, e = gt & 1;
        g_blob[gt]        = oW1[d * 32 + 2 * tp + e];
        g_blob[1744 + gt] = sW1[d * 32 + 2 * tp + e];
    }
    if (gt >= 128 && gt < 160) {
        int t = gt - 128;
        g_blob[128 + t]  = ob1[t];
        g_blob[1184 + t] = ob2[t];
        g_blob[1872 + t] = sb1[t];
        g_blob[2928 + t] = sb2[t];
        g_blob[4512 + t] = gb1[t];
    }
    if (gt >= 160 && gt < 176) { g_blob[1728 + gt - 160] = ob3[gt - 160]; }
    if (gt >= 176 && gt < 192) { g_blob[3472 + gt - 176] = sb3[gt - 176]; }
    if (gt >= 192 && gt < 256) { g_blob[4544 + gt - 192] = gW2[gt - 192]; }
    if (gt >= 256 && gt < 258) { g_blob[4608 + gt - 256] = gb2[gt - 256]; }
    if (gt < 1024) {
        int j = gt >> 5, i = gt & 31;
        g_blob[160  + j * 32 + i] = oW2[i * 32 + j];
        g_blob[1904 + j * 32 + i] = sW2[i * 32 + j];
        g_blob[3488 + j * 32 + i] = gW1[i * 32 + j];
    }
    if (gt >= 1024 && gt < 1536) {
        int idx = gt - 1024;
        g_blob[1216 + idx] = oW3[idx];
        g_blob[2960 + idx] = sW3[idx];
    }
}

// ---------------- Kernel A: other-agent MLP on TENSOR pipe (fp16, 32 MMA/row) -------
// Scalar-diet version: single-fp16 x (no split), half-domain relu packs.
// 4 CTAs/SM for 4 warps/SMSP of scalar/tensor overlap.
__global__ __launch_bounds__(128, 4)
void hmma_kernel(const float* __restrict__ x,
                 const int*   __restrict__ selp,
                 const float* __restrict__ oW1, const float* __restrict__ ob1,
                 const float* __restrict__ oW2, const float* __restrict__ ob2,
                 const float* __restrict__ oW3, const float* __restrict__ ob3)
{
    const int lane  = threadIdx.x & 31;
    const int warp  = threadIdx.x >> 5;
    const int gwarp = blockIdx.x * 4 + warp;      // 0..4095
    const int g  = lane >> 2;                      // 0..7
    const int tc = lane & 3;                       // 0..3
    const int sel = selp[0];
    const uint Z = 0u;

    // ---- B fragments (single fp16) ----
    uint B1[4];
    #pragma unroll
    for (int n = 0; n < 4; ++n) {
        float wa = 0.0f, wb = 0.0f;
        if (tc < 2) {
            wa = oW1[(2 * tc) * 32 + 8 * n + g];
            wb = oW1[(2 * tc + 1) * 32 + 8 * n + g];
        }
        B1[n] = pack_f16(wa, wb);
    }
    uint B2[4][2][2];
    #pragma unroll
    for (int n = 0; n < 4; ++n) {
        #pragma unroll
        for (int ks = 0; ks < 2; ++ks) {
            int c  = 8 * n + g;
            int k0 = 16 * ks + 2 * tc;
            B2[n][ks][0] = pack_f16(oW2[k0 * 32 + c],       oW2[(k0 + 1) * 32 + c]);
            B2[n][ks][1] = pack_f16(oW2[(k0 + 8) * 32 + c], oW2[(k0 + 9) * 32 + c]);
        }
    }
    uint B3[2][2][2];
    #pragma unroll
    for (int n = 0; n < 2; ++n) {
        #pragma unroll
        for (int ks = 0; ks < 2; ++ks) {
            int c  = 8 * n + g;
            int k0 = 16 * ks + 2 * tc;
            B3[n][ks][0] = pack_f16(oW3[k0 * 16 + c],       oW3[(k0 + 1) * 16 + c]);
            B3[n][ks][1] = pack_f16(oW3[(k0 + 8) * 16 + c], oW3[(k0 + 9) * 16 + c]);
        }
    }
    float2 bz1[4], bz2[4], bz3[2];
    #pragma unroll
    for (int n = 0; n < 4; ++n) {
        bz1[n] = *reinterpret_cast<const float2*>(ob1 + 8 * n + 2 * tc);
        bz2[n] = *reinterpret_cast<const float2*>(ob2 + 8 * n + 2 * tc);
    }
    #pragma unroll
    for (int n = 0; n < 2; ++n)
        bz3[n] = *reinterpret_cast<const float2*>(ob3 + 8 * n + 2 * tc);

    // per-lane x offsets (within a row of 128 floats)
    const int offA0 = (g) * 4 + (tc & 1) * 2;
    const int offB0 = (8 + g) * 4 + (tc & 1) * 2;
    const int offA1 = (16 + g) * 4 + (tc & 1) * 2;
    const int offB1 = (24 + g) * 4 + (tc & 1) * 2;

    const float* xr = x + (size_t)(gwarp * 16) * 128;

    // prefetch first row
    float2 nA0 = *reinterpret_cast<const float2*>(xr + offA0);
    float2 nB0 = *reinterpret_cast<const float2*>(xr + offB0);
    float2 nA1 = *reinterpret_cast<const float2*>(xr + offA1);
    float2 nB1 = *reinterpret_cast<const float2*>(xr + offB1);

    // ---- persistent row loop: 16 rows per warp ----
    for (int it = 0; it < 16; ++it) {
        const int row = gwarp * 16 + it;
        float2 cA[2] = { nA0, nA1 };
        float2 cB[2] = { nB0, nB1 };
        if (it < 15) {
            const float* xn = xr + 128;
            nA0 = *reinterpret_cast<const float2*>(xn + offA0);
            nB0 = *reinterpret_cast<const float2*>(xn + offB0);
            nA1 = *reinterpret_cast<const float2*>(xn + offA1);
            nB1 = *reinterpret_cast<const float2*>(xn + offB1);
        }
        xr += 128;

        float v00 = 0.f, v01 = 0.f, v10 = 0.f, v11 = 0.f;

        #pragma unroll
        for (int m = 0; m < 2; ++m) {
            // single fp16 x (x in [0,1), rounding ~2^-12 avg — within budget)
            uint a0 = pack_f16(cA[m].x, cA[m].y);
            uint a1 = pack_f16(cB[m].x, cB[m].y);

            // ---- G1: one MMA per n-tile ----
            float4 D1[4];
            #pragma unroll
            for (int n = 0; n < 4; ++n) {
                D1[n] = make_float4(bz1[n].x, bz1[n].y, bz1[n].x, bz1[n].y);
                mma_f16(D1[n], a0, a1, Z, Z, B1[n], Z);
            }

            // ---- G2: cvt + half-domain relu; 1 MMA per n per ks ----
            float4 D2[4];
            #pragma unroll
            for (int n = 0; n < 4; ++n)
                D2[n] = make_float4(bz2[n].x, bz2[n].y, bz2[n].x, bz2[n].y);
            #pragma unroll
            for (int ks = 0; ks < 2; ++ks) {
                uint A0 = packrelu_f16(D1[2 * ks].x,     D1[2 * ks].y);
                uint A1 = packrelu_f16(D1[2 * ks].z,     D1[2 * ks].w);
                uint A2 = packrelu_f16(D1[2 * ks + 1].x, D1[2 * ks + 1].y);
                uint A3 = packrelu_f16(D1[2 * ks + 1].z, D1[2 * ks + 1].w);
                #pragma unroll
                for (int n = 0; n < 4; ++n)
                    mma_f16(D2[n], A0, A1, A2, A3, B2[n][ks][0], B2[n][ks][1]);
            }

            // ---- G3 ----
            float4 D3[2];
            #pragma unroll
            for (int n = 0; n < 2; ++n)
                D3[n] = make_float4(bz3[n].x, bz3[n].y, bz3[n].x, bz3[n].y);
            #pragma unroll
            for (int ks = 0; ks < 2; ++ks) {
                uint A0 = packrelu_f16(D2[2 * ks].x,     D2[2 * ks].y);
                uint A1 = packrelu_f16(D2[2 * ks].z,     D2[2 * ks].w);
                uint A2 = packrelu_f16(D2[2 * ks + 1].x, D2[2 * ks + 1].y);
                uint A3 = packrelu_f16(D2[2 * ks + 1].z, D2[2 * ks + 1].w);
                #pragma unroll
                for (int n = 0; n < 2; ++n)
                    mma_f16(D3[n], A0, A1, A2, A3, B3[n][ks][0], B3[n][ks][1]);
            }

            // epilogue: relu, mask selected agent, accumulate
            float mk0 = (m * 16 + g == sel) ? 0.0f : 1.0f;
            float mk1 = (m * 16 + 8 + g == sel) ? 0.0f : 1.0f;
            v00 += relu_(D3[0].x) * mk0 + relu_(D3[0].z) * mk1;
            v01 += relu_(D3[0].y) * mk0 + relu_(D3[0].w) * mk1;
            v10 += relu_(D3[1].x) * mk0 + relu_(D3[1].z) * mk1;
            v11 += relu_(D3[1].y) * mk0 + relu_(D3[1].w) * mk1;
        }

        ull p0 = pk2(v00, v01);
        ull p1 = pk2(v10, v11);
        #pragma unroll
        for (int off = 4; off < 32; off <<= 1) {
            p0 = fadd2(p0, __shfl_xor_sync(FULL, p0, off));
            p1 = fadd2(p1, __shfl_xor_sync(FULL, p1, off));
        }
        if (lane < 4) {
            g_sum[(size_t)row * 8 + tc]     = p0;
            g_sum[(size_t)row * 8 + 4 + tc] = p1;
        }
    }
}

// ---------------- Kernel B: tail (unchanged, full fp32) ----------------
__global__ __launch_bounds__(256)
void tail_kernel(const float* __restrict__ x,
                 const int*   __restrict__ selp,
                 float* __restrict__ out_q)
{
    const int row = blockIdx.x * 256 + threadIdx.x;
    const int sel = selp[0];

    const float4 xs = reinterpret_cast<const float4*>(x)[row * 32 + sel];

    ull so_p[8];
    {
        const ulonglong2* src = reinterpret_cast<const ulonglong2*>(g_sum + (size_t)row * 8);
        #pragma unroll
        for (int r = 0; r < 4; ++r) {
            ulonglong2 v = src[r];
            so_p[2 * r + 0] = v.x;
            so_p[2 * r + 1] = v.y;
        }
    }

    ull xd0 = pk2(xs.x, xs.x), xd1 = pk2(xs.y, xs.y);
    ull xd2 = pk2(xs.z, xs.z), xd3 = pk2(xs.w, xs.w);
    ull h1[16];
    {
        const ulonglong2* w1 = reinterpret_cast<const ulonglong2*>(c_w + 1744);
        const ull* b1 = reinterpret_cast<const ull*>(c_w + 1872);
        #pragma unroll
        for (int t = 0; t < 16; ++t) {
            ulonglong2 wA = w1[2 * t + 0];
            ulonglong2 wB = w1[2 * t + 1];
            ull a = ffma2(xd0, wA.x, b1[t]);
            a = ffma2(xd1, wA.y, a);
            a = ffma2(xd2, wB.x, a);
            a = ffma2(xd3, wB.y, a);
            h1[t] = relu2(a);
        }
    }

    ull acc3[8];
    {
        const ull* b3 = reinterpret_cast<const ull*>(c_w + 3472);
        #pragma unroll
        for (int t = 0; t < 8; ++t) acc3[t] = b3[t];
    }
    #pragma unroll 4
    for (int j = 0; j < 32; ++j) {
        ull a = 0ull;
        const ulonglong2* w2 = reinterpret_cast<const ulonglong2*>(c_w + 1904 + j * 32);
        #pragma unroll
        for (int q = 0; q < 8; ++q) {
            ulonglong2 w = w2[q];
            a = ffma2(h1[2 * q + 0], w.x, a);
            a = ffma2(h1[2 * q + 1], w.y, a);
        }
        float s = relu_(hadd2(a) + c_w[2928 + j]);
        ull p = pk2(s, s);
        const ulonglong2* w3 = reinterpret_cast<const ulonglong2*>(c_w + 2960 + j * 16);
        #pragma unroll
        for (int r = 0; r < 4; ++r) {
            ulonglong2 w = w3[r];
            acc3[2 * r + 0] = ffma2(p, w.x, acc3[2 * r + 0]);
            acc3[2 * r + 1] = ffma2(p, w.y, acc3[2 * r + 1]);
        }
    }
    #pragma unroll
    for (int t = 0; t < 8; ++t) acc3[t] = relu2(acc3[t]);

    float q0 = 0.0f, q1 = 0.0f;
    #pragma unroll 4
    for (int m = 0; m < 32; ++m) {
        ull a = 0ull;
        const ulonglong2* wg = reinterpret_cast<const ulonglong2*>(c_w + 3488 + m * 32);
        #pragma unroll
        for (int q = 0; q < 4; ++q) {
            ulonglong2 w = wg[q];
            a = ffma2(acc3[2 * q + 0], w.x, a);
            a = ffma2(acc3[2 * q + 1], w.y, a);
        }
        #pragma unroll
        for (int q = 0; q < 4; ++q) {
            ulonglong2 w = wg[4 + q];
            a = ffma2(so_p[2 * q + 0], w.x, a);
            a = ffma2(so_p[2 * q + 1], w.y, a);
        }
        float gg = relu_(hadd2(a) + c_w[4512 + m]);
        q0 = fmaf(gg, c_w[4544 + 2 * m + 0], q0);
        q1 = fmaf(gg, c_w[4544 + 2 * m + 1], q1);
    }

    int act = (int)xs.w;
    act = act < 0 ? 0 : (act > 1 ? 1 : act);
    out_q[row] = act ? (q1 + c_w[4609]) : (q0 + c_w[4608]);
}

extern "C" void kernel_launch(void* const* d_in, const int* in_sizes, int n_in,
                              void* d_out, int out_size)
{
    (void)in_sizes; (void)n_in; (void)out_size;

    static cudaStream_t s2 = nullptr;
    static cudaEvent_t evFork = nullptr, evJoin = nullptr;
    if (!s2) {
        cudaStreamCreateWithFlags(&s2, cudaStreamNonBlocking);
        cudaEventCreateWithFlags(&evFork, cudaEventDisableTiming);
        cudaEventCreateWithFlags(&evJoin, cudaEventDisableTiming);
    }

    void* dst = nullptr;
    void* src = nullptr;
    cudaGetSymbolAddress(&dst, c_w);
    cudaGetSymbolAddress(&src, g_blob);

    // Fork: pack + memcpy on s2, overlapped with hmma on the main stream.
    cudaEventRecord(evFork, 0);
    cudaStreamWaitEvent(s2, evFork, 0);

    pack_kernel<<<8, 256, 0, s2>>>(
        (const float*)d_in[2],  (const float*)d_in[3],
        (const float*)d_in[4],  (const float*)d_in[5],
        (const float*)d_in[6],  (const float*)d_in[7],
        (const float*)d_in[8],  (const float*)d_in[9],
        (const float*)d_in[10], (const float*)d_in[11],
        (const float*)d_in[12], (const float*)d_in[13],
        (const float*)d_in[14], (const float*)d_in[15],
        (const float*)d_in[16], (const float*)d_in[17]);
    cudaMemcpyAsync(dst, src, CW_TOTAL * sizeof(float),
                    cudaMemcpyDeviceToDevice, s2);
    cudaEventRecord(evJoin, s2);

    // Kernel A (tensor pipe) on the main stream, independent of c_w.
    hmma_kernel<<<1024, 128>>>(
        (const float*)d_in[0], (const int*)d_in[1],
        (const float*)d_in[2], (const float*)d_in[3],
        (const float*)d_in[4], (const float*)d_in[5],
        (const float*)d_in[6], (const float*)d_in[7]);

    // Join: tail needs both g_sum (main stream) and c_w (s2).
    cudaStreamWaitEvent(0, evJoin, 0);
    tail_kernel<<<256, 256>>>((const float*)d_in[0], (const int*)d_in[1],
                              (float*)d_out);
}